// round 13
// baseline (speedup 1.0000x reference)
#include <cuda_runtime.h>
#include <cuda_bf16.h>
#include <cstdint>

#define M_ROWS 65536
#define B_ROWS 2048
#define DD 13
#define K1P 320
#define N2P 640
#define N3P 128

// ---------- global scratch ----------
__device__ __nv_bfloat16 g_h1hi[(size_t)M_ROWS * K1P];
__device__ __nv_bfloat16 g_h1lo[(size_t)M_ROWS * K1P];
__device__ __nv_bfloat16 g_h2hi[(size_t)M_ROWS * N2P];
__device__ __nv_bfloat16 g_h2lo[(size_t)M_ROWS * N2P];
__device__ __nv_bfloat16 g_w2hi[N2P * K1P];
__device__ __nv_bfloat16 g_w2lo[N2P * K1P];
__device__ __nv_bfloat16 g_w3hi[N3P * N2P];
__device__ __nv_bfloat16 g_w3lo[N3P * N2P];
__device__ __nv_bfloat16 g_t1hi[(size_t)M_ROWS * 16];
__device__ __nv_bfloat16 g_t1lo[(size_t)M_ROWS * 16];
__device__ __nv_bfloat16 g_t2hi[B_ROWS * 16];
__device__ __nv_bfloat16 g_t2lo[B_ROWS * 16];
__device__ int g_maxkey[B_ROWS];

// ---------- helpers ----------
__device__ __forceinline__ uint32_t smem_u32(const void* p) {
    uint32_t a;
    asm("{ .reg .u64 t; cvta.to.shared.u64 t, %1; cvt.u32.u64 %0, t; }" : "=r"(a) : "l"(p));
    return a;
}
__device__ __forceinline__ void cp16(uint32_t saddr, const void* gaddr) {
    asm volatile("cp.async.cg.shared.global [%0], [%1], 16;" :: "r"(saddr), "l"(gaddr));
}
#define CP_COMMIT() asm volatile("cp.async.commit_group;" ::: "memory")
#define CP_WAIT1()  asm volatile("cp.async.wait_group 1;" ::: "memory")
__device__ __forceinline__ void ldm_x4(uint32_t& r0, uint32_t& r1, uint32_t& r2,
                                       uint32_t& r3, uint32_t addr) {
    asm volatile("ldmatrix.sync.aligned.m8n8.x4.shared.b16 {%0,%1,%2,%3}, [%4];"
                 : "=r"(r0), "=r"(r1), "=r"(r2), "=r"(r3) : "r"(addr));
}
__device__ __forceinline__ void mma_bf16(float* c, const uint32_t* a,
                                         uint32_t b0, uint32_t b1) {
    asm volatile(
        "mma.sync.aligned.m16n8k16.row.col.f32.bf16.bf16.f32 "
        "{%0,%1,%2,%3}, {%4,%5,%6,%7}, {%8,%9}, {%0,%1,%2,%3};"
        : "+f"(c[0]), "+f"(c[1]), "+f"(c[2]), "+f"(c[3])
        : "r"(a[0]), "r"(a[1]), "r"(a[2]), "r"(a[3]), "r"(b0), "r"(b1));
}
__device__ __forceinline__ int fkey(float f) {
    int i = __float_as_int(f);
    return (i >= 0) ? i : (i ^ 0x7FFFFFFF);
}
__device__ __forceinline__ float finv(int k) {
    return __int_as_float((k >= 0) ? k : (k ^ 0x7FFFFFFF));
}
__device__ __forceinline__ void bsplit(float v, __nv_bfloat16& hi, __nv_bfloat16& lo) {
    hi = __float2bfloat16(v);
    lo = __float2bfloat16(v - __bfloat162float(hi));
}

// ============================================================
// k_head: merged k_l1 (blocks 0..1023) + prep/pre (blocks 1024..1039)
// ============================================================
#define L1_SMEM ((4200 + 300 + 64 * 304) * 4)
__global__ void __launch_bounds__(256)
k_head(const float* __restrict__ memory, const float* __restrict__ W1,
       const float* __restrict__ b1, const float* __restrict__ W2,
       const float* __restrict__ W3, const float* __restrict__ value) {
    extern __shared__ float sf[];
    const int t = threadIdx.x;

    if (blockIdx.x >= 1024) {
        const int pb = blockIdx.x - 1024;
        const int gid = pb * 256 + t;
        const int pstride = 16 * 256;
        for (int i = gid; i < N2P * K1P; i += pstride) {
            int n = i / K1P, k = i % K1P;
            float v = (n < 600 && k < 300) ? W2[n * 300 + k] : 0.f;
            __nv_bfloat16 h, l; bsplit(v, h, l);
            g_w2hi[i] = h; g_w2lo[i] = l;
        }
        for (int i = gid; i < N3P * N2P; i += pstride) {
            int c = i / N2P, k = i % N2P;
            float v = (c < 100 && k < 600) ? W3[c * 600 + k] : 0.f;
            __nv_bfloat16 h, l; bsplit(v, h, l);
            g_w3hi[i] = h; g_w3lo[i] = l;
        }
        if (gid < B_ROWS) {
            float v[DD]; float ss = 0.f;
#pragma unroll
            for (int d = 0; d < DD; d++) { v[d] = value[gid * DD + d]; ss += v[d] * v[d]; }
            float inv = 1.0f / fmaxf(sqrtf(ss), 1e-8f);
#pragma unroll
            for (int p = 0; p < 8; p++) {
                float v0 = (2 * p < DD) ? v[2 * p] * inv : 0.f;
                float v1 = (2 * p + 1 < DD) ? v[2 * p + 1] * inv : 0.f;
                __nv_bfloat16 h0, l0, h1, l1;
                bsplit(v0, h0, l0); bsplit(v1, h1, l1);
                __nv_bfloat162 vh; vh.x = h0; vh.y = h1;
                __nv_bfloat162 vl; vl.x = l0; vl.y = l1;
                *reinterpret_cast<__nv_bfloat162*>(g_t2hi + gid * 16 + 2 * p) = vh;
                *reinterpret_cast<__nv_bfloat162*>(g_t2lo + gid * 16 + 2 * p) = vl;
            }
            g_maxkey[gid] = fkey(-3.0e38f);
        }
        return;
    }

    const int row0 = blockIdx.x * 64;
    for (int i = t; i < 300 * DD; i += 256) { int k = i / DD, d = i % DD; sf[k * 14 + d] = W1[i]; }
    for (int i = t; i < 300; i += 256) sf[4200 + i] = b1[i];
    const int m = t & 63, kg = t >> 6;
    float x[DD];
#pragma unroll
    for (int d = 0; d < DD; d++) x[d] = memory[(row0 + m) * DD + d];
    __syncthreads();
    for (int k = kg * 75; k < kg * 75 + 75; k++) {
        const float* wr = sf + k * 14;
        float acc = sf[4200 + k];
#pragma unroll
        for (int d = 0; d < DD; d++) acc += x[d] * wr[d];
        sf[4500 + m * 304 + k] = fmaxf(acc, 0.f);
    }
    __syncthreads();
    for (int i = t; i < 64 * 160; i += 256) {
        int row = i / 160, kp = (i % 160) * 2;
        float v0 = (kp < 300) ? sf[4500 + row * 304 + kp] : 0.f;
        float v1 = (kp + 1 < 300) ? sf[4500 + row * 304 + kp + 1] : 0.f;
        __nv_bfloat16 h0, l0, h1, l1;
        bsplit(v0, h0, l0); bsplit(v1, h1, l1);
        __nv_bfloat162 ph; ph.x = h0; ph.y = h1;
        __nv_bfloat162 pl; pl.x = l0; pl.y = l1;
        size_t o = (size_t)(row0 + row) * K1P + kp;
        *reinterpret_cast<__nv_bfloat162*>(g_h1hi + o) = ph;
        *reinterpret_cast<__nv_bfloat162*>(g_h1lo + o) = pl;
    }
}

// ============================================================
// k_l2: warp split-K (unchanged from R12)
// ============================================================
#define STG2 16384
#define L2_SMEM (1024 + 3 * STG2)
__device__ __forceinline__ void l2_stage(uint32_t bufs, int t, int m0, int n0, int kc) {
#pragma unroll
    for (int ii = 0; ii < 4; ii++) {
        int i = t + ii * 256;
        int c16 = i & 3;
        int r = (i >> 2) & 63;
        int pl = (i >> 8) & 1;
        int sel = i >> 9;
        int phys = c16 ^ ((r >> 1) & 3);
        if (sel == 0) {
            const char* src = pl ? (const char*)g_h1lo : (const char*)g_h1hi;
            cp16(bufs + pl * 4096 + r * 64 + phys * 16,
                 src + ((size_t)(m0 + r) * K1P + kc + c16 * 8) * 2);
        } else {
            const char* src = pl ? (const char*)g_w2lo : (const char*)g_w2hi;
            cp16(bufs + 8192 + pl * 4096 + r * 64 + phys * 16,
                 src + ((size_t)(n0 + r) * K1P + kc + c16 * 8) * 2);
        }
    }
}

__global__ void __launch_bounds__(256, 3)
k_l2(const float* __restrict__ b2) {
    extern __shared__ char smc[];
    const uint32_t sb = smem_u32(smc);
    float* biasS = reinterpret_cast<float*>(smc);
    const int t = threadIdx.x, warp = t >> 5, lane = t & 31;
    const int n0 = blockIdx.x * 64, m0 = blockIdx.y * 64;
    const int wpos = warp & 3, wk = warp >> 2;
    const int m_warp = (wpos & 1) * 32, n_warp = (wpos >> 1) * 32;

    for (int i = t; i < 64; i += 256) { int j = n0 + i; biasS[i] = (j < 600) ? b2[j] : 0.f; }

    const int rA0 = m_warp + (lane & 7) + ((lane >> 3) & 1) * 8;
    const int cA  = lane >> 4;
    const int rB0 = n_warp + (lane & 7) + (lane >> 4) * 8;
    const int cB  = (lane >> 3) & 1;

    uint32_t offA[2], offB[2];
#pragma unroll
    for (int f = 0; f < 2; f++) {
        int rA = rA0 + f * 16;
        offA[f] = (uint32_t)(rA * 64 + (((cA + 2 * wk) ^ ((rA >> 1) & 3))) * 16);
        int rB = rB0 + f * 16;
        offB[f] = (uint32_t)(8192 + rB * 64 + (((cB + 2 * wk) ^ ((rB >> 1) & 3))) * 16);
    }

    float acc[2][4][4];
#pragma unroll
    for (int f = 0; f < 2; f++)
#pragma unroll
        for (int n = 0; n < 4; n++)
#pragma unroll
            for (int q = 0; q < 4; q++) acc[f][n][q] = 0.f;

    l2_stage(sb + 1024, t, m0, n0, 0); CP_COMMIT();
    l2_stage(sb + 1024 + STG2, t, m0, n0, 32); CP_COMMIT();

    for (int ch = 0; ch < 10; ch++) {
        CP_WAIT1();
        __syncthreads();
        if (ch + 2 < 10)
            l2_stage(sb + 1024 + ((ch + 2) % 3) * STG2, t, m0, n0, (ch + 2) * 32);
        CP_COMMIT();

        const uint32_t buf = sb + 1024 + (ch % 3) * STG2;
        uint32_t aH[2][4], aL[2][4], bH[2][4], bL[2][4];
#pragma unroll
        for (int f = 0; f < 2; f++) {
            uint32_t ad = buf + offA[f];
            ldm_x4(aH[f][0], aH[f][1], aH[f][2], aH[f][3], ad);
            ldm_x4(aL[f][0], aL[f][1], aL[f][2], aL[f][3], ad + 4096);
        }
#pragma unroll
        for (int bp = 0; bp < 2; bp++) {
            uint32_t bd = buf + offB[bp];
            ldm_x4(bH[bp][0], bH[bp][1], bH[bp][2], bH[bp][3], bd);
            ldm_x4(bL[bp][0], bL[bp][1], bL[bp][2], bL[bp][3], bd + 4096);
        }
#pragma unroll
        for (int bp = 0; bp < 2; bp++)
#pragma unroll
            for (int f = 0; f < 2; f++)
#pragma unroll
                for (int h = 0; h < 2; h++)
                    mma_bf16(acc[f][bp * 2 + h], aH[f], bH[bp][2 * h], bH[bp][2 * h + 1]);
#pragma unroll
        for (int bp = 0; bp < 2; bp++)
#pragma unroll
            for (int f = 0; f < 2; f++)
#pragma unroll
                for (int h = 0; h < 2; h++)
                    mma_bf16(acc[f][bp * 2 + h], aH[f], bL[bp][2 * h], bL[bp][2 * h + 1]);
#pragma unroll
        for (int bp = 0; bp < 2; bp++)
#pragma unroll
            for (int f = 0; f < 2; f++)
#pragma unroll
                for (int h = 0; h < 2; h++)
                    mma_bf16(acc[f][bp * 2 + h], aL[f], bH[bp][2 * h], bH[bp][2 * h + 1]);
    }
    __syncthreads();

    float* red = reinterpret_cast<float*>(smc + 1024);
    if (wk == 1) {
        const int col = wpos * 32 + lane;
#pragma unroll
        for (int f = 0; f < 2; f++)
#pragma unroll
            for (int nf = 0; nf < 4; nf++)
#pragma unroll
                for (int q = 0; q < 4; q++)
                    red[(f * 16 + nf * 4 + q) * 128 + col] = acc[f][nf][q];
    }
    __syncthreads();

#define L2_EHI 17408
#define L2_ELO 25600
    if (wk == 0) {
        const int col32 = wpos * 32 + lane;
#pragma unroll
        for (int f = 0; f < 2; f++) {
            int r0 = m_warp + f * 16 + (lane >> 2);
#pragma unroll
            for (int nf = 0; nf < 4; nf++) {
                int col = n_warp + nf * 8 + (lane & 3) * 2;
                float b0 = biasS[col], b1 = biasS[col + 1];
#pragma unroll
                for (int hrow = 0; hrow < 2; hrow++) {
                    int r = r0 + hrow * 8;
                    float z0 = acc[f][nf][2 * hrow]
                             + red[(f * 16 + nf * 4 + 2 * hrow) * 128 + col32] + b0;
                    float z1 = acc[f][nf][2 * hrow + 1]
                             + red[(f * 16 + nf * 4 + 2 * hrow + 1) * 128 + col32] + b1;
                    z0 = (z0 > 0.f) ? z0 : 0.01f * z0;
                    z1 = (z1 > 0.f) ? z1 : 0.01f * z1;
                    __nv_bfloat16 h0, l0, h1, l1;
                    bsplit(z0, h0, l0); bsplit(z1, h1, l1);
                    __nv_bfloat162 vh; vh.x = h0; vh.y = h1;
                    __nv_bfloat162 vl; vl.x = l0; vl.y = l1;
                    *reinterpret_cast<__nv_bfloat162*>(smc + L2_EHI + r * 128 + col * 2) = vh;
                    *reinterpret_cast<__nv_bfloat162*>(smc + L2_ELO + r * 128 + col * 2) = vl;
                }
            }
        }
    }
    __syncthreads();
    for (int i = t; i < 1024; i += 256) {
        int pl = i >> 9, r = (i >> 3) & 63, cc = i & 7;
        char* dst = pl ? (char*)g_h2lo : (char*)g_h2hi;
        *reinterpret_cast<float4*>(dst + ((size_t)(m0 + r) * N2P + n0) * 2 + cc * 16) =
            *reinterpret_cast<const float4*>(smc + (pl ? L2_ELO : L2_EHI) + r * 128 + cc * 16);
    }
}

// ============================================================
// k_l3: persistent grid 888, CTA 64m x 128n, K=640/20 chunks (unchanged)
// ============================================================
#define STG3 24576
#define L3_SMEM (1024 + 3 * STG3)
#define L3_GRID 888
__device__ __forceinline__ void l3_stage(uint32_t bufs, int t, int m0, int kc) {
#pragma unroll
    for (int ii = 0; ii < 6; ii++) {
        int i = t + ii * 256;
        int c16 = i & 3;
        if (i < 512) {
            int pl = i >> 8, r = (i >> 2) & 63;
            const char* src = pl ? (const char*)g_h2lo : (const char*)g_h2hi;
            int phys = c16 ^ ((r >> 1) & 3);
            cp16(bufs + pl * 4096 + r * 64 + phys * 16,
                 src + ((size_t)(m0 + r) * N2P + kc + c16 * 8) * 2);
        } else {
            int j = i - 512;
            int pl = j >> 9, r = (j >> 2) & 127;
            const char* src = pl ? (const char*)g_w3lo : (const char*)g_w3hi;
            int phys = c16 ^ ((r >> 1) & 3);
            cp16(bufs + 8192 + pl * 8192 + r * 64 + phys * 16,
                 src + ((size_t)r * N2P + kc + c16 * 8) * 2);
        }
    }
}

__global__ void __launch_bounds__(256, 3)
k_l3(const float* __restrict__ b3, const float* __restrict__ b4,
     const float* __restrict__ W4) {
    extern __shared__ char smc[];
    const uint32_t sb = smem_u32(smc);
    float* b3s = reinterpret_cast<float*>(smc);
    float* b4s = reinterpret_cast<float*>(smc + 512);
    const int t = threadIdx.x, warp = t >> 5, lane = t & 31;
    const int m_warp = (warp & 1) * 32, n_warp = (warp >> 1) * 32;

    for (int i = t; i < 128; i += 256) b3s[i] = (i < 100) ? b3[i] : 0.f;
    if (t < 16) b4s[t] = (t < DD) ? b4[t] : 0.f;

    const int rA0 = m_warp + (lane & 7) + ((lane >> 3) & 1) * 8;
    const int cA  = lane >> 4;
    const int rB0 = n_warp + (lane & 7) + (lane >> 4) * 8;
    const int cB  = (lane >> 3) & 1;

    uint32_t offA[2][2], offB[2][2];
#pragma unroll
    for (int f = 0; f < 2; f++)
#pragma unroll
        for (int ks = 0; ks < 2; ks++) {
            int rA = rA0 + f * 16;
            offA[f][ks] = (uint32_t)(rA * 64 + (((cA + 2 * ks) ^ ((rA >> 1) & 3))) * 16);
            int rB = rB0 + f * 16;
            offB[f][ks] = (uint32_t)(8192 + rB * 64 + (((cB + 2 * ks) ^ ((rB >> 1) & 3))) * 16);
        }

    for (int tile = blockIdx.x; tile < 1024; tile += L3_GRID) {
        const int m0 = tile * 64;

        float acc[2][4][4];
#pragma unroll
        for (int f = 0; f < 2; f++)
#pragma unroll
            for (int n = 0; n < 4; n++)
#pragma unroll
                for (int q = 0; q < 4; q++) acc[f][n][q] = 0.f;

        __syncthreads();
        l3_stage(sb + 1024, t, m0, 0); CP_COMMIT();
        l3_stage(sb + 1024 + STG3, t, m0, 32); CP_COMMIT();

        for (int ch = 0; ch < 20; ch++) {
            CP_WAIT1();
            __syncthreads();
            if (ch + 2 < 20)
                l3_stage(sb + 1024 + ((ch + 2) % 3) * STG3, t, m0, (ch + 2) * 32);
            CP_COMMIT();

            const uint32_t buf = sb + 1024 + (ch % 3) * STG3;
#pragma unroll
            for (int ks = 0; ks < 2; ks++) {
                uint32_t aH[2][4], aL[2][4], bH[2][4], bL[2][4];
#pragma unroll
                for (int f = 0; f < 2; f++) {
                    uint32_t ad = buf + offA[f][ks];
                    ldm_x4(aH[f][0], aH[f][1], aH[f][2], aH[f][3], ad);
                    ldm_x4(aL[f][0], aL[f][1], aL[f][2], aL[f][3], ad + 4096);
                }
#pragma unroll
                for (int bp = 0; bp < 2; bp++) {
                    uint32_t bd = buf + offB[bp][ks];
                    ldm_x4(bH[bp][0], bH[bp][1], bH[bp][2], bH[bp][3], bd);
                    ldm_x4(bL[bp][0], bL[bp][1], bL[bp][2], bL[bp][3], bd + 8192);
                }
#pragma unroll
                for (int bp = 0; bp < 2; bp++)
#pragma unroll
                    for (int f = 0; f < 2; f++)
#pragma unroll
                        for (int h = 0; h < 2; h++)
                            mma_bf16(acc[f][bp * 2 + h], aH[f], bH[bp][2 * h], bH[bp][2 * h + 1]);
#pragma unroll
                for (int bp = 0; bp < 2; bp++)
#pragma unroll
                    for (int f = 0; f < 2; f++)
#pragma unroll
                        for (int h = 0; h < 2; h++)
                            mma_bf16(acc[f][bp * 2 + h], aH[f], bL[bp][2 * h], bL[bp][2 * h + 1]);
#pragma unroll
                for (int bp = 0; bp < 2; bp++)
#pragma unroll
                    for (int f = 0; f < 2; f++)
#pragma unroll
                        for (int h = 0; h < 2; h++)
                            mma_bf16(acc[f][bp * 2 + h], aL[f], bH[bp][2 * h], bH[bp][2 * h + 1]);
            }
        }
        __syncthreads();

        float* h3 = reinterpret_cast<float*>(smc + 1024);
        float* W4s = reinterpret_cast<float*>(smc + 35072);
        float* sp  = reinterpret_cast<float*>(smc + 41472);
#pragma unroll
        for (int f = 0; f < 2; f++) {
            int r0 = m_warp + f * 16 + (lane >> 2);
#pragma unroll
            for (int nf = 0; nf < 4; nf++) {
                int col = n_warp + nf * 8 + (lane & 3) * 2;
                const float* c = acc[f][nf];
#pragma unroll
                for (int hrow = 0; hrow < 2; hrow++) {
                    int r = r0 + hrow * 8;
                    h3[r * 133 + col]     = fmaxf(c[2 * hrow] + b3s[col], 0.f);
                    h3[r * 133 + col + 1] = fmaxf(c[2 * hrow + 1] + b3s[col + 1], 0.f);
                }
            }
        }
        for (int i = t; i < 13 * 112; i += 256) {
            int d = i / 112, c = i % 112;
            W4s[i] = (c < 100) ? W4[d * 100 + c] : 0.f;
        }
        __syncthreads();

        {
            const int r = t & 63, g = t >> 6;
            const float* hr = h3 + r * 133 + g * 25;
            const float* wb = W4s + g * 25;
            float p[DD];
#pragma unroll
            for (int d = 0; d < DD; d++) p[d] = 0.f;
#pragma unroll 5
            for (int c = 0; c < 25; c++) {
                float h = hr[c];
#pragma unroll
                for (int d = 0; d < DD; d++) p[d] += h * wb[d * 112 + c];
            }
#pragma unroll
            for (int d = 0; d < DD; d++) sp[(r * 4 + g) * 14 + d] = p[d];
        }
        __syncthreads();

        if (t < 64) {
            float t1[DD];
            float ss = 0.f;
#pragma unroll
            for (int d = 0; d < DD; d++) {
                float s_ = b4s[d] + sp[(t * 4 + 0) * 14 + d] + sp[(t * 4 + 1) * 14 + d]
                         + sp[(t * 4 + 2) * 14 + d] + sp[(t * 4 + 3) * 14 + d];
                float v = (s_ > 0.f) ? s_ : 0.01f * s_;
                t1[d] = v;
                ss += v * v;
            }
            float inv = 1.0f / fmaxf(sqrtf(ss), 1e-8f);
            size_t row = (size_t)(m0 + t) * 16;
#pragma unroll
            for (int p = 0; p < 8; p++) {
                float v0 = (2 * p < DD) ? t1[2 * p] * inv : 0.f;
                float v1 = (2 * p + 1 < DD) ? t1[2 * p + 1] * inv : 0.f;
                __nv_bfloat16 h0, l0, h1, l1;
                bsplit(v0, h0, l0); bsplit(v1, h1, l1);
                __nv_bfloat162 vh; vh.x = h0; vh.y = h1;
                __nv_bfloat162 vl; vl.x = l0; vl.y = l1;
                *reinterpret_cast<__nv_bfloat162*>(g_t1hi + row + 2 * p) = vh;
                *reinterpret_cast<__nv_bfloat162*>(g_t1lo + row + 2 * p) = vl;
            }
        }
    }
}

// ============================================================
// k_sim_t v2: warp = (b-half 64 rows) x (m-quarter).
// A fragments (4 pairs) loaded ONCE; per step one B hi/lo load
// (1 KB) feeds 24 MMAs. B swizzle bit is step-invariant.
// smem unchanged: sA 8KB @0; sB hi @8192, lo @24576. 40KB total.
// ============================================================
__global__ void __launch_bounds__(256) k_sim_t() {
    __shared__ char sm[40960];
    const uint32_t sb = smem_u32(sm);
    const int t = threadIdx.x, warp = t >> 5, lane = t & 31;
    const int wb = warp & 1;        // b-half (64 rows)
    const int wm = warp >> 1;       // m-quarter (8 of 32 steps)
    const int b0 = blockIdx.x * 128;
    const int mbase = blockIdx.y * 2048;

    // stage t2 split block (once)
    for (int i = t; i < 512; i += 256) {
        int pl = i >> 8, j = i & 255, row = j >> 1, half = j & 1;
        const char* src = pl ? (const char*)g_t2lo : (const char*)g_t2hi;
        int ph = half ^ ((row >> 2) & 1);
        *reinterpret_cast<float4*>(sm + pl * 4096 + row * 32 + ph * 16) =
            *reinterpret_cast<const float4*>(src + ((size_t)(b0 + row) * 16 + half * 8) * 2);
    }
    __syncthreads();

    // A fragments: 4 pairs covering 64 b rows, loaded once
    uint32_t aH[4][4], aL[4][4];
    const int cA = lane >> 4;
#pragma unroll
    for (int g = 0; g < 4; g++) {
        int rA = wb * 64 + g * 16 + (lane & 7) + ((lane >> 3) & 1) * 8;
        uint32_t aAddr = sb + rA * 32 + ((cA ^ ((rA >> 2) & 1))) * 16;
        ldm_x4(aH[g][0], aH[g][1], aH[g][2], aH[g][3], aAddr);
        ldm_x4(aL[g][0], aL[g][1], aL[g][2], aL[g][3], aAddr + 4096);
    }

    // B base offset: swizzle bit (rB>>2)&1 is invariant under +16 row steps
    const int rB = (lane & 7) + (lane >> 4) * 8;
    const int cB = (lane >> 3) & 1;
    const uint32_t bOff = (uint32_t)(8192 + rB * 32 + ((cB ^ ((rB >> 2) & 1))) * 16);

    float mx[4][2];
#pragma unroll
    for (int g = 0; g < 4; g++) { mx[g][0] = -3.0e38f; mx[g][1] = -3.0e38f; }

    for (int c = 0; c < 4; c++) {
        __syncthreads();
        for (int i = t; i < 2048; i += 256) {
            int pl = i >> 10, j = i & 1023, row = j >> 1, half = j & 1;
            const char* src = pl ? (const char*)g_t1lo : (const char*)g_t1hi;
            int ph = half ^ ((row >> 2) & 1);
            *reinterpret_cast<float4*>(sm + 8192 + pl * 16384 + row * 32 + ph * 16) =
                *reinterpret_cast<const float4*>(
                    src + ((size_t)(mbase + c * 512 + row) * 16 + half * 8) * 2);
        }
        __syncthreads();

        uint32_t bAddr = sb + bOff + (uint32_t)(wm * 8) * 512;
#pragma unroll 2
        for (int s = 0; s < 8; s++) {
            uint32_t bH[4], bL[4];
            ldm_x4(bH[0], bH[1], bH[2], bH[3], bAddr);
            ldm_x4(bL[0], bL[1], bL[2], bL[3], bAddr + 16384);
            bAddr += 512;
#pragma unroll
            for (int g = 0; g < 4; g++) {
                float a0[4] = {0.f, 0.f, 0.f, 0.f};
                float a1[4] = {0.f, 0.f, 0.f, 0.f};
                mma_bf16(a0, aH[g], bH[0], bH[1]);
                mma_bf16(a1, aH[g], bH[2], bH[3]);
                mma_bf16(a0, aH[g], bL[0], bL[1]);
                mma_bf16(a1, aH[g], bL[2], bL[3]);
                mma_bf16(a0, aL[g], bH[0], bH[1]);
                mma_bf16(a1, aL[g], bH[2], bH[3]);
                mx[g][0] = fmaxf(mx[g][0], fmaxf(fmaxf(a0[0], a0[1]), fmaxf(a1[0], a1[1])));
                mx[g][1] = fmaxf(mx[g][1], fmaxf(fmaxf(a0[2], a0[3]), fmaxf(a1[2], a1[3])));
            }
        }
    }

    // reduce across the 4 col-lanes sharing each row, then atomicMax
#pragma unroll
    for (int g = 0; g < 4; g++) {
        mx[g][0] = fmaxf(mx[g][0], __shfl_xor_sync(0xFFFFFFFF, mx[g][0], 1));
        mx[g][0] = fmaxf(mx[g][0], __shfl_xor_sync(0xFFFFFFFF, mx[g][0], 2));
        mx[g][1] = fmaxf(mx[g][1], __shfl_xor_sync(0xFFFFFFFF, mx[g][1], 1));
        mx[g][1] = fmaxf(mx[g][1], __shfl_xor_sync(0xFFFFFFFF, mx[g][1], 2));
    }
    if ((lane & 3) == 0) {
        const int base = b0 + wb * 64 + (lane >> 2);
#pragma unroll
        for (int g = 0; g < 4; g++) {
            atomicMax(&g_maxkey[base + g * 16], fkey(mx[g][0]));
            atomicMax(&g_maxkey[base + g * 16 + 8], fkey(mx[g][1]));
        }
    }
}

// ============================================================
__global__ void k_fin(float* __restrict__ out) {
    int b = blockIdx.x * blockDim.x + threadIdx.x;
    if (b < B_ROWS) out[b] = 23.0f * finv(g_maxkey[b]);
}

// ============================================================
extern "C" void kernel_launch(void* const* d_in, const int* in_sizes, int n_in,
                              void* d_out, int out_size) {
    const float* memory = (const float*)d_in[0];
    const float* value  = (const float*)d_in[1];
    const float* W1 = (const float*)d_in[2];
    const float* b1 = (const float*)d_in[3];
    const float* W2 = (const float*)d_in[4];
    const float* b2 = (const float*)d_in[5];
    const float* W3 = (const float*)d_in[6];
    const float* b3 = (const float*)d_in[7];
    const float* W4 = (const float*)d_in[8];
    const float* b4 = (const float*)d_in[9];

    cudaFuncSetAttribute(k_head, cudaFuncAttributeMaxDynamicSharedMemorySize, L1_SMEM);
    cudaFuncSetAttribute(k_l2, cudaFuncAttributeMaxDynamicSharedMemorySize, L2_SMEM);
    cudaFuncSetAttribute(k_l3, cudaFuncAttributeMaxDynamicSharedMemorySize, L3_SMEM);

    k_head<<<1040, 256, L1_SMEM>>>(memory, W1, b1, W2, W3, value);
    k_l2<<<dim3(10, 1024), 256, L2_SMEM>>>(b2);
    k_l3<<<L3_GRID, 256, L3_SMEM>>>(b3, b4, W4);
    k_sim_t<<<dim3(16, 32), 256>>>();
    k_fin<<<8, 256>>>((float*)d_out);
}

// round 14
// speedup vs baseline: 1.0014x; 1.0014x over previous
#include <cuda_runtime.h>
#include <cuda_bf16.h>
#include <cstdint>

#define M_ROWS 65536
#define B_ROWS 2048
#define DD 13
#define K1P 320
#define N2P 640
#define N3P 128

// ---------- global scratch ----------
__device__ __nv_bfloat16 g_h1hi[(size_t)M_ROWS * K1P];
__device__ __nv_bfloat16 g_h1lo[(size_t)M_ROWS * K1P];
__device__ __nv_bfloat16 g_h2hi[(size_t)M_ROWS * N2P];
__device__ __nv_bfloat16 g_h2lo[(size_t)M_ROWS * N2P];
__device__ __nv_bfloat16 g_w2hi[N2P * K1P];
__device__ __nv_bfloat16 g_w2lo[N2P * K1P];
__device__ __nv_bfloat16 g_w3hi[N3P * N2P];
__device__ __nv_bfloat16 g_w3lo[N3P * N2P];
__device__ __nv_bfloat16 g_t1hi[(size_t)M_ROWS * 16];
__device__ __nv_bfloat16 g_t1lo[(size_t)M_ROWS * 16];
__device__ __nv_bfloat16 g_t2hi[B_ROWS * 16];
__device__ __nv_bfloat16 g_t2lo[B_ROWS * 16];
__device__ int g_maxkey[B_ROWS];

// ---------- helpers ----------
__device__ __forceinline__ uint32_t smem_u32(const void* p) {
    uint32_t a;
    asm("{ .reg .u64 t; cvta.to.shared.u64 t, %1; cvt.u32.u64 %0, t; }" : "=r"(a) : "l"(p));
    return a;
}
__device__ __forceinline__ void cp16(uint32_t saddr, const void* gaddr) {
    asm volatile("cp.async.cg.shared.global [%0], [%1], 16;" :: "r"(saddr), "l"(gaddr));
}
#define CP_COMMIT() asm volatile("cp.async.commit_group;" ::: "memory")
#define CP_WAIT1()  asm volatile("cp.async.wait_group 1;" ::: "memory")
__device__ __forceinline__ void ldm_x4(uint32_t& r0, uint32_t& r1, uint32_t& r2,
                                       uint32_t& r3, uint32_t addr) {
    asm volatile("ldmatrix.sync.aligned.m8n8.x4.shared.b16 {%0,%1,%2,%3}, [%4];"
                 : "=r"(r0), "=r"(r1), "=r"(r2), "=r"(r3) : "r"(addr));
}
__device__ __forceinline__ void mma_bf16(float* c, const uint32_t* a,
                                         uint32_t b0, uint32_t b1) {
    asm volatile(
        "mma.sync.aligned.m16n8k16.row.col.f32.bf16.bf16.f32 "
        "{%0,%1,%2,%3}, {%4,%5,%6,%7}, {%8,%9}, {%0,%1,%2,%3};"
        : "+f"(c[0]), "+f"(c[1]), "+f"(c[2]), "+f"(c[3])
        : "r"(a[0]), "r"(a[1]), "r"(a[2]), "r"(a[3]), "r"(b0), "r"(b1));
}
__device__ __forceinline__ int fkey(float f) {
    int i = __float_as_int(f);
    return (i >= 0) ? i : (i ^ 0x7FFFFFFF);
}
__device__ __forceinline__ float finv(int k) {
    return __int_as_float((k >= 0) ? k : (k ^ 0x7FFFFFFF));
}
__device__ __forceinline__ void bsplit(float v, __nv_bfloat16& hi, __nv_bfloat16& lo) {
    hi = __float2bfloat16(v);
    lo = __float2bfloat16(v - __bfloat162float(hi));
}

// ============================================================
// k_head: merged k_l1 (blocks 0..1023) + prep/pre (blocks 1024..1039)
// ============================================================
#define L1_SMEM ((4200 + 300 + 64 * 304) * 4)
__global__ void __launch_bounds__(256)
k_head(const float* __restrict__ memory, const float* __restrict__ W1,
       const float* __restrict__ b1, const float* __restrict__ W2,
       const float* __restrict__ W3, const float* __restrict__ value) {
    extern __shared__ float sf[];
    const int t = threadIdx.x;

    if (blockIdx.x >= 1024) {
        const int pb = blockIdx.x - 1024;
        const int gid = pb * 256 + t;
        const int pstride = 16 * 256;
        for (int i = gid; i < N2P * K1P; i += pstride) {
            int n = i / K1P, k = i % K1P;
            float v = (n < 600 && k < 300) ? W2[n * 300 + k] : 0.f;
            __nv_bfloat16 h, l; bsplit(v, h, l);
            g_w2hi[i] = h; g_w2lo[i] = l;
        }
        for (int i = gid; i < N3P * N2P; i += pstride) {
            int c = i / N2P, k = i % N2P;
            float v = (c < 100 && k < 600) ? W3[c * 600 + k] : 0.f;
            __nv_bfloat16 h, l; bsplit(v, h, l);
            g_w3hi[i] = h; g_w3lo[i] = l;
        }
        if (gid < B_ROWS) {
            float v[DD]; float ss = 0.f;
#pragma unroll
            for (int d = 0; d < DD; d++) { v[d] = value[gid * DD + d]; ss += v[d] * v[d]; }
            float inv = 1.0f / fmaxf(sqrtf(ss), 1e-8f);
#pragma unroll
            for (int p = 0; p < 8; p++) {
                float v0 = (2 * p < DD) ? v[2 * p] * inv : 0.f;
                float v1 = (2 * p + 1 < DD) ? v[2 * p + 1] * inv : 0.f;
                __nv_bfloat16 h0, l0, h1, l1;
                bsplit(v0, h0, l0); bsplit(v1, h1, l1);
                __nv_bfloat162 vh; vh.x = h0; vh.y = h1;
                __nv_bfloat162 vl; vl.x = l0; vl.y = l1;
                *reinterpret_cast<__nv_bfloat162*>(g_t2hi + gid * 16 + 2 * p) = vh;
                *reinterpret_cast<__nv_bfloat162*>(g_t2lo + gid * 16 + 2 * p) = vl;
            }
            g_maxkey[gid] = fkey(-3.0e38f);
        }
        return;
    }

    const int row0 = blockIdx.x * 64;
    for (int i = t; i < 300 * DD; i += 256) { int k = i / DD, d = i % DD; sf[k * 14 + d] = W1[i]; }
    for (int i = t; i < 300; i += 256) sf[4200 + i] = b1[i];
    const int m = t & 63, kg = t >> 6;
    float x[DD];
#pragma unroll
    for (int d = 0; d < DD; d++) x[d] = memory[(row0 + m) * DD + d];
    __syncthreads();
    for (int k = kg * 75; k < kg * 75 + 75; k++) {
        const float* wr = sf + k * 14;
        float acc = sf[4200 + k];
#pragma unroll
        for (int d = 0; d < DD; d++) acc += x[d] * wr[d];
        sf[4500 + m * 304 + k] = fmaxf(acc, 0.f);
    }
    __syncthreads();
    for (int i = t; i < 64 * 160; i += 256) {
        int row = i / 160, kp = (i % 160) * 2;
        float v0 = (kp < 300) ? sf[4500 + row * 304 + kp] : 0.f;
        float v1 = (kp + 1 < 300) ? sf[4500 + row * 304 + kp + 1] : 0.f;
        __nv_bfloat16 h0, l0, h1, l1;
        bsplit(v0, h0, l0); bsplit(v1, h1, l1);
        __nv_bfloat162 ph; ph.x = h0; ph.y = h1;
        __nv_bfloat162 pl; pl.x = l0; pl.y = l1;
        size_t o = (size_t)(row0 + row) * K1P + kp;
        *reinterpret_cast<__nv_bfloat162*>(g_h1hi + o) = ph;
        *reinterpret_cast<__nv_bfloat162*>(g_h1lo + o) = pl;
    }
}

// ============================================================
// k_l2: warp split-K (unchanged from R12)
// ============================================================
#define STG2 16384
#define L2_SMEM (1024 + 3 * STG2)
__device__ __forceinline__ void l2_stage(uint32_t bufs, int t, int m0, int n0, int kc) {
#pragma unroll
    for (int ii = 0; ii < 4; ii++) {
        int i = t + ii * 256;
        int c16 = i & 3;
        int r = (i >> 2) & 63;
        int pl = (i >> 8) & 1;
        int sel = i >> 9;
        int phys = c16 ^ ((r >> 1) & 3);
        if (sel == 0) {
            const char* src = pl ? (const char*)g_h1lo : (const char*)g_h1hi;
            cp16(bufs + pl * 4096 + r * 64 + phys * 16,
                 src + ((size_t)(m0 + r) * K1P + kc + c16 * 8) * 2);
        } else {
            const char* src = pl ? (const char*)g_w2lo : (const char*)g_w2hi;
            cp16(bufs + 8192 + pl * 4096 + r * 64 + phys * 16,
                 src + ((size_t)(n0 + r) * K1P + kc + c16 * 8) * 2);
        }
    }
}

__global__ void __launch_bounds__(256, 3)
k_l2(const float* __restrict__ b2) {
    extern __shared__ char smc[];
    const uint32_t sb = smem_u32(smc);
    float* biasS = reinterpret_cast<float*>(smc);
    const int t = threadIdx.x, warp = t >> 5, lane = t & 31;
    const int n0 = blockIdx.x * 64, m0 = blockIdx.y * 64;
    const int wpos = warp & 3, wk = warp >> 2;
    const int m_warp = (wpos & 1) * 32, n_warp = (wpos >> 1) * 32;

    for (int i = t; i < 64; i += 256) { int j = n0 + i; biasS[i] = (j < 600) ? b2[j] : 0.f; }

    const int rA0 = m_warp + (lane & 7) + ((lane >> 3) & 1) * 8;
    const int cA  = lane >> 4;
    const int rB0 = n_warp + (lane & 7) + (lane >> 4) * 8;
    const int cB  = (lane >> 3) & 1;

    uint32_t offA[2], offB[2];
#pragma unroll
    for (int f = 0; f < 2; f++) {
        int rA = rA0 + f * 16;
        offA[f] = (uint32_t)(rA * 64 + (((cA + 2 * wk) ^ ((rA >> 1) & 3))) * 16);
        int rB = rB0 + f * 16;
        offB[f] = (uint32_t)(8192 + rB * 64 + (((cB + 2 * wk) ^ ((rB >> 1) & 3))) * 16);
    }

    float acc[2][4][4];
#pragma unroll
    for (int f = 0; f < 2; f++)
#pragma unroll
        for (int n = 0; n < 4; n++)
#pragma unroll
            for (int q = 0; q < 4; q++) acc[f][n][q] = 0.f;

    l2_stage(sb + 1024, t, m0, n0, 0); CP_COMMIT();
    l2_stage(sb + 1024 + STG2, t, m0, n0, 32); CP_COMMIT();

    for (int ch = 0; ch < 10; ch++) {
        CP_WAIT1();
        __syncthreads();
        if (ch + 2 < 10)
            l2_stage(sb + 1024 + ((ch + 2) % 3) * STG2, t, m0, n0, (ch + 2) * 32);
        CP_COMMIT();

        const uint32_t buf = sb + 1024 + (ch % 3) * STG2;
        uint32_t aH[2][4], aL[2][4], bH[2][4], bL[2][4];
#pragma unroll
        for (int f = 0; f < 2; f++) {
            uint32_t ad = buf + offA[f];
            ldm_x4(aH[f][0], aH[f][1], aH[f][2], aH[f][3], ad);
            ldm_x4(aL[f][0], aL[f][1], aL[f][2], aL[f][3], ad + 4096);
        }
#pragma unroll
        for (int bp = 0; bp < 2; bp++) {
            uint32_t bd = buf + offB[bp];
            ldm_x4(bH[bp][0], bH[bp][1], bH[bp][2], bH[bp][3], bd);
            ldm_x4(bL[bp][0], bL[bp][1], bL[bp][2], bL[bp][3], bd + 4096);
        }
#pragma unroll
        for (int bp = 0; bp < 2; bp++)
#pragma unroll
            for (int f = 0; f < 2; f++)
#pragma unroll
                for (int h = 0; h < 2; h++)
                    mma_bf16(acc[f][bp * 2 + h], aH[f], bH[bp][2 * h], bH[bp][2 * h + 1]);
#pragma unroll
        for (int bp = 0; bp < 2; bp++)
#pragma unroll
            for (int f = 0; f < 2; f++)
#pragma unroll
                for (int h = 0; h < 2; h++)
                    mma_bf16(acc[f][bp * 2 + h], aH[f], bL[bp][2 * h], bL[bp][2 * h + 1]);
#pragma unroll
        for (int bp = 0; bp < 2; bp++)
#pragma unroll
            for (int f = 0; f < 2; f++)
#pragma unroll
                for (int h = 0; h < 2; h++)
                    mma_bf16(acc[f][bp * 2 + h], aL[f], bH[bp][2 * h], bH[bp][2 * h + 1]);
    }
    __syncthreads();

    float* red = reinterpret_cast<float*>(smc + 1024);
    if (wk == 1) {
        const int col = wpos * 32 + lane;
#pragma unroll
        for (int f = 0; f < 2; f++)
#pragma unroll
            for (int nf = 0; nf < 4; nf++)
#pragma unroll
                for (int q = 0; q < 4; q++)
                    red[(f * 16 + nf * 4 + q) * 128 + col] = acc[f][nf][q];
    }
    __syncthreads();

#define L2_EHI 17408
#define L2_ELO 25600
    if (wk == 0) {
        const int col32 = wpos * 32 + lane;
#pragma unroll
        for (int f = 0; f < 2; f++) {
            int r0 = m_warp + f * 16 + (lane >> 2);
#pragma unroll
            for (int nf = 0; nf < 4; nf++) {
                int col = n_warp + nf * 8 + (lane & 3) * 2;
                float b0 = biasS[col], b1 = biasS[col + 1];
#pragma unroll
                for (int hrow = 0; hrow < 2; hrow++) {
                    int r = r0 + hrow * 8;
                    float z0 = acc[f][nf][2 * hrow]
                             + red[(f * 16 + nf * 4 + 2 * hrow) * 128 + col32] + b0;
                    float z1 = acc[f][nf][2 * hrow + 1]
                             + red[(f * 16 + nf * 4 + 2 * hrow + 1) * 128 + col32] + b1;
                    z0 = (z0 > 0.f) ? z0 : 0.01f * z0;
                    z1 = (z1 > 0.f) ? z1 : 0.01f * z1;
                    __nv_bfloat16 h0, l0, h1, l1;
                    bsplit(z0, h0, l0); bsplit(z1, h1, l1);
                    __nv_bfloat162 vh; vh.x = h0; vh.y = h1;
                    __nv_bfloat162 vl; vl.x = l0; vl.y = l1;
                    *reinterpret_cast<__nv_bfloat162*>(smc + L2_EHI + r * 128 + col * 2) = vh;
                    *reinterpret_cast<__nv_bfloat162*>(smc + L2_ELO + r * 128 + col * 2) = vl;
                }
            }
        }
    }
    __syncthreads();
    for (int i = t; i < 1024; i += 256) {
        int pl = i >> 9, r = (i >> 3) & 63, cc = i & 7;
        char* dst = pl ? (char*)g_h2lo : (char*)g_h2hi;
        *reinterpret_cast<float4*>(dst + ((size_t)(m0 + r) * N2P + n0) * 2 + cc * 16) =
            *reinterpret_cast<const float4*>(smc + (pl ? L2_ELO : L2_EHI) + r * 128 + cc * 16);
    }
}

// ============================================================
// k_l3: persistent grid 888, CTA 64m x 128n, K=640/20 chunks (unchanged)
// ============================================================
#define STG3 24576
#define L3_SMEM (1024 + 3 * STG3)
#define L3_GRID 888
__device__ __forceinline__ void l3_stage(uint32_t bufs, int t, int m0, int kc) {
#pragma unroll
    for (int ii = 0; ii < 6; ii++) {
        int i = t + ii * 256;
        int c16 = i & 3;
        if (i < 512) {
            int pl = i >> 8, r = (i >> 2) & 63;
            const char* src = pl ? (const char*)g_h2lo : (const char*)g_h2hi;
            int phys = c16 ^ ((r >> 1) & 3);
            cp16(bufs + pl * 4096 + r * 64 + phys * 16,
                 src + ((size_t)(m0 + r) * N2P + kc + c16 * 8) * 2);
        } else {
            int j = i - 512;
            int pl = j >> 9, r = (j >> 2) & 127;
            const char* src = pl ? (const char*)g_w3lo : (const char*)g_w3hi;
            int phys = c16 ^ ((r >> 1) & 3);
            cp16(bufs + 8192 + pl * 8192 + r * 64 + phys * 16,
                 src + ((size_t)r * N2P + kc + c16 * 8) * 2);
        }
    }
}

__global__ void __launch_bounds__(256, 3)
k_l3(const float* __restrict__ b3, const float* __restrict__ b4,
     const float* __restrict__ W4) {
    extern __shared__ char smc[];
    const uint32_t sb = smem_u32(smc);
    float* b3s = reinterpret_cast<float*>(smc);
    float* b4s = reinterpret_cast<float*>(smc + 512);
    const int t = threadIdx.x, warp = t >> 5, lane = t & 31;
    const int m_warp = (warp & 1) * 32, n_warp = (warp >> 1) * 32;

    for (int i = t; i < 128; i += 256) b3s[i] = (i < 100) ? b3[i] : 0.f;
    if (t < 16) b4s[t] = (t < DD) ? b4[t] : 0.f;

    const int rA0 = m_warp + (lane & 7) + ((lane >> 3) & 1) * 8;
    const int cA  = lane >> 4;
    const int rB0 = n_warp + (lane & 7) + (lane >> 4) * 8;
    const int cB  = (lane >> 3) & 1;

    uint32_t offA[2][2], offB[2][2];
#pragma unroll
    for (int f = 0; f < 2; f++)
#pragma unroll
        for (int ks = 0; ks < 2; ks++) {
            int rA = rA0 + f * 16;
            offA[f][ks] = (uint32_t)(rA * 64 + (((cA + 2 * ks) ^ ((rA >> 1) & 3))) * 16);
            int rB = rB0 + f * 16;
            offB[f][ks] = (uint32_t)(8192 + rB * 64 + (((cB + 2 * ks) ^ ((rB >> 1) & 3))) * 16);
        }

    for (int tile = blockIdx.x; tile < 1024; tile += L3_GRID) {
        const int m0 = tile * 64;

        float acc[2][4][4];
#pragma unroll
        for (int f = 0; f < 2; f++)
#pragma unroll
            for (int n = 0; n < 4; n++)
#pragma unroll
                for (int q = 0; q < 4; q++) acc[f][n][q] = 0.f;

        __syncthreads();
        l3_stage(sb + 1024, t, m0, 0); CP_COMMIT();
        l3_stage(sb + 1024 + STG3, t, m0, 32); CP_COMMIT();

        for (int ch = 0; ch < 20; ch++) {
            CP_WAIT1();
            __syncthreads();
            if (ch + 2 < 20)
                l3_stage(sb + 1024 + ((ch + 2) % 3) * STG3, t, m0, (ch + 2) * 32);
            CP_COMMIT();

            const uint32_t buf = sb + 1024 + (ch % 3) * STG3;
#pragma unroll
            for (int ks = 0; ks < 2; ks++) {
                uint32_t aH[2][4], aL[2][4], bH[2][4], bL[2][4];
#pragma unroll
                for (int f = 0; f < 2; f++) {
                    uint32_t ad = buf + offA[f][ks];
                    ldm_x4(aH[f][0], aH[f][1], aH[f][2], aH[f][3], ad);
                    ldm_x4(aL[f][0], aL[f][1], aL[f][2], aL[f][3], ad + 4096);
                }
#pragma unroll
                for (int bp = 0; bp < 2; bp++) {
                    uint32_t bd = buf + offB[bp][ks];
                    ldm_x4(bH[bp][0], bH[bp][1], bH[bp][2], bH[bp][3], bd);
                    ldm_x4(bL[bp][0], bL[bp][1], bL[bp][2], bL[bp][3], bd + 8192);
                }
#pragma unroll
                for (int bp = 0; bp < 2; bp++)
#pragma unroll
                    for (int f = 0; f < 2; f++)
#pragma unroll
                        for (int h = 0; h < 2; h++)
                            mma_bf16(acc[f][bp * 2 + h], aH[f], bH[bp][2 * h], bH[bp][2 * h + 1]);
#pragma unroll
                for (int bp = 0; bp < 2; bp++)
#pragma unroll
                    for (int f = 0; f < 2; f++)
#pragma unroll
                        for (int h = 0; h < 2; h++)
                            mma_bf16(acc[f][bp * 2 + h], aH[f], bL[bp][2 * h], bL[bp][2 * h + 1]);
#pragma unroll
                for (int bp = 0; bp < 2; bp++)
#pragma unroll
                    for (int f = 0; f < 2; f++)
#pragma unroll
                        for (int h = 0; h < 2; h++)
                            mma_bf16(acc[f][bp * 2 + h], aL[f], bH[bp][2 * h], bH[bp][2 * h + 1]);
            }
        }
        __syncthreads();

        float* h3 = reinterpret_cast<float*>(smc + 1024);
        float* W4s = reinterpret_cast<float*>(smc + 35072);
        float* sp  = reinterpret_cast<float*>(smc + 41472);
#pragma unroll
        for (int f = 0; f < 2; f++) {
            int r0 = m_warp + f * 16 + (lane >> 2);
#pragma unroll
            for (int nf = 0; nf < 4; nf++) {
                int col = n_warp + nf * 8 + (lane & 3) * 2;
                const float* c = acc[f][nf];
#pragma unroll
                for (int hrow = 0; hrow < 2; hrow++) {
                    int r = r0 + hrow * 8;
                    h3[r * 133 + col]     = fmaxf(c[2 * hrow] + b3s[col], 0.f);
                    h3[r * 133 + col + 1] = fmaxf(c[2 * hrow + 1] + b3s[col + 1], 0.f);
                }
            }
        }
        for (int i = t; i < 13 * 112; i += 256) {
            int d = i / 112, c = i % 112;
            W4s[i] = (c < 100) ? W4[d * 100 + c] : 0.f;
        }
        __syncthreads();

        {
            const int r = t & 63, g = t >> 6;
            const float* hr = h3 + r * 133 + g * 25;
            const float* wb = W4s + g * 25;
            float p[DD];
#pragma unroll
            for (int d = 0; d < DD; d++) p[d] = 0.f;
#pragma unroll 5
            for (int c = 0; c < 25; c++) {
                float h = hr[c];
#pragma unroll
                for (int d = 0; d < DD; d++) p[d] += h * wb[d * 112 + c];
            }
#pragma unroll
            for (int d = 0; d < DD; d++) sp[(r * 4 + g) * 14 + d] = p[d];
        }
        __syncthreads();

        if (t < 64) {
            float t1[DD];
            float ss = 0.f;
#pragma unroll
            for (int d = 0; d < DD; d++) {
                float s_ = b4s[d] + sp[(t * 4 + 0) * 14 + d] + sp[(t * 4 + 1) * 14 + d]
                         + sp[(t * 4 + 2) * 14 + d] + sp[(t * 4 + 3) * 14 + d];
                float v = (s_ > 0.f) ? s_ : 0.01f * s_;
                t1[d] = v;
                ss += v * v;
            }
            float inv = 1.0f / fmaxf(sqrtf(ss), 1e-8f);
            size_t row = (size_t)(m0 + t) * 16;
#pragma unroll
            for (int p = 0; p < 8; p++) {
                float v0 = (2 * p < DD) ? t1[2 * p] * inv : 0.f;
                float v1 = (2 * p + 1 < DD) ? t1[2 * p + 1] * inv : 0.f;
                __nv_bfloat16 h0, l0, h1, l1;
                bsplit(v0, h0, l0); bsplit(v1, h1, l1);
                __nv_bfloat162 vh; vh.x = h0; vh.y = h1;
                __nv_bfloat162 vl; vl.x = l0; vl.y = l1;
                *reinterpret_cast<__nv_bfloat162*>(g_t1hi + row + 2 * p) = vh;
                *reinterpret_cast<__nv_bfloat162*>(g_t1lo + row + 2 * p) = vl;
            }
        }
    }
}

// ============================================================
// k_sim_t v3: warp = (b-quarter 32 rows) x (m-half 16 steps).
// A fragments: 2 pairs loaded once (16 regs). Low regs -> 4 CTAs/SM
// -> grid 512 fits in ONE wave (592 slots).
// smem: sA 8KB @0; sB hi @8192, lo @24576. 40KB.
// ============================================================
__global__ void __launch_bounds__(256, 4) k_sim_t() {
    __shared__ char sm[40960];
    const uint32_t sb = smem_u32(sm);
    const int t = threadIdx.x, warp = t >> 5, lane = t & 31;
    const int wq = warp & 3;        // b-quarter (32 rows)
    const int wh = warp >> 2;       // m-half (16 of 32 steps)
    const int b0 = blockIdx.x * 128;
    const int mbase = blockIdx.y * 2048;

    // stage t2 split block (once)
    for (int i = t; i < 512; i += 256) {
        int pl = i >> 8, j = i & 255, row = j >> 1, half = j & 1;
        const char* src = pl ? (const char*)g_t2lo : (const char*)g_t2hi;
        int ph = half ^ ((row >> 2) & 1);
        *reinterpret_cast<float4*>(sm + pl * 4096 + row * 32 + ph * 16) =
            *reinterpret_cast<const float4*>(src + ((size_t)(b0 + row) * 16 + half * 8) * 2);
    }
    __syncthreads();

    // A fragments: 2 pairs covering 32 b rows, loaded once
    uint32_t aH[2][4], aL[2][4];
    const int cA = lane >> 4;
#pragma unroll
    for (int g = 0; g < 2; g++) {
        int rA = wq * 32 + g * 16 + (lane & 7) + ((lane >> 3) & 1) * 8;
        uint32_t aAddr = sb + rA * 32 + ((cA ^ ((rA >> 2) & 1))) * 16;
        ldm_x4(aH[g][0], aH[g][1], aH[g][2], aH[g][3], aAddr);
        ldm_x4(aL[g][0], aL[g][1], aL[g][2], aL[g][3], aAddr + 4096);
    }

    // B base: swizzle bit (rB>>2)&1 invariant under +16 row steps
    const int rB = (lane & 7) + (lane >> 4) * 8;
    const int cB = (lane >> 3) & 1;
    const uint32_t bOff = (uint32_t)(8192 + rB * 32 + ((cB ^ ((rB >> 2) & 1))) * 16);

    float mx[2][2];
#pragma unroll
    for (int g = 0; g < 2; g++) { mx[g][0] = -3.0e38f; mx[g][1] = -3.0e38f; }

    for (int c = 0; c < 4; c++) {
        __syncthreads();
        for (int i = t; i < 2048; i += 256) {
            int pl = i >> 10, j = i & 1023, row = j >> 1, half = j & 1;
            const char* src = pl ? (const char*)g_t1lo : (const char*)g_t1hi;
            int ph = half ^ ((row >> 2) & 1);
            *reinterpret_cast<float4*>(sm + 8192 + pl * 16384 + row * 32 + ph * 16) =
                *reinterpret_cast<const float4*>(
                    src + ((size_t)(mbase + c * 512 + row) * 16 + half * 8) * 2);
        }
        __syncthreads();

        uint32_t bAddr = sb + bOff + (uint32_t)(wh * 16) * 512;
#pragma unroll 4
        for (int s = 0; s < 16; s++) {
            uint32_t bH[4], bL[4];
            ldm_x4(bH[0], bH[1], bH[2], bH[3], bAddr);
            ldm_x4(bL[0], bL[1], bL[2], bL[3], bAddr + 16384);
            bAddr += 512;
#pragma unroll
            for (int g = 0; g < 2; g++) {
                float a0[4] = {0.f, 0.f, 0.f, 0.f};
                float a1[4] = {0.f, 0.f, 0.f, 0.f};
                mma_bf16(a0, aH[g], bH[0], bH[1]);
                mma_bf16(a1, aH[g], bH[2], bH[3]);
                mma_bf16(a0, aH[g], bL[0], bL[1]);
                mma_bf16(a1, aH[g], bL[2], bL[3]);
                mma_bf16(a0, aL[g], bH[0], bH[1]);
                mma_bf16(a1, aL[g], bH[2], bH[3]);
                mx[g][0] = fmaxf(mx[g][0], fmaxf(fmaxf(a0[0], a0[1]), fmaxf(a1[0], a1[1])));
                mx[g][1] = fmaxf(mx[g][1], fmaxf(fmaxf(a0[2], a0[3]), fmaxf(a1[2], a1[3])));
            }
        }
    }

    // reduce across the 4 col-lanes sharing each row, then atomicMax
#pragma unroll
    for (int g = 0; g < 2; g++) {
        mx[g][0] = fmaxf(mx[g][0], __shfl_xor_sync(0xFFFFFFFF, mx[g][0], 1));
        mx[g][0] = fmaxf(mx[g][0], __shfl_xor_sync(0xFFFFFFFF, mx[g][0], 2));
        mx[g][1] = fmaxf(mx[g][1], __shfl_xor_sync(0xFFFFFFFF, mx[g][1], 1));
        mx[g][1] = fmaxf(mx[g][1], __shfl_xor_sync(0xFFFFFFFF, mx[g][1], 2));
    }
    if ((lane & 3) == 0) {
        const int base = b0 + wq * 32 + (lane >> 2);
#pragma unroll
        for (int g = 0; g < 2; g++) {
            atomicMax(&g_maxkey[base + g * 16], fkey(mx[g][0]));
            atomicMax(&g_maxkey[base + g * 16 + 8], fkey(mx[g][1]));
        }
    }
}

// ============================================================
__global__ void k_fin(float* __restrict__ out) {
    int b = blockIdx.x * blockDim.x + threadIdx.x;
    if (b < B_ROWS) out[b] = 23.0f * finv(g_maxkey[b]);
}

// ============================================================
extern "C" void kernel_launch(void* const* d_in, const int* in_sizes, int n_in,
                              void* d_out, int out_size) {
    const float* memory = (const float*)d_in[0];
    const float* value  = (const float*)d_in[1];
    const float* W1 = (const float*)d_in[2];
    const float* b1 = (const float*)d_in[3];
    const float* W2 = (const float*)d_in[4];
    const float* b2 = (const float*)d_in[5];
    const float* W3 = (const float*)d_in[6];
    const float* b3 = (const float*)d_in[7];
    const float* W4 = (const float*)d_in[8];
    const float* b4 = (const float*)d_in[9];

    cudaFuncSetAttribute(k_head, cudaFuncAttributeMaxDynamicSharedMemorySize, L1_SMEM);
    cudaFuncSetAttribute(k_l2, cudaFuncAttributeMaxDynamicSharedMemorySize, L2_SMEM);
    cudaFuncSetAttribute(k_l3, cudaFuncAttributeMaxDynamicSharedMemorySize, L3_SMEM);

    k_head<<<1040, 256, L1_SMEM>>>(memory, W1, b1, W2, W3, value);
    k_l2<<<dim3(10, 1024), 256, L2_SMEM>>>(b2);
    k_l3<<<L3_GRID, 256, L3_SMEM>>>(b3, b4, W4);
    k_sim_t<<<dim3(16, 32), 256>>>();
    k_fin<<<8, 256>>>((float*)d_out);
}

// round 15
// speedup vs baseline: 1.0099x; 1.0085x over previous
#include <cuda_runtime.h>
#include <cuda_bf16.h>
#include <cstdint>

#define M_ROWS 65536
#define B_ROWS 2048
#define DD 13
#define K1P 320
#define N2P 640
#define N3P 128

// ---------- global scratch ----------
__device__ __nv_bfloat16 g_h1hi[(size_t)M_ROWS * K1P];
__device__ __nv_bfloat16 g_h1lo[(size_t)M_ROWS * K1P];
__device__ __nv_bfloat16 g_h2hi[(size_t)M_ROWS * N2P];
__device__ __nv_bfloat16 g_h2lo[(size_t)M_ROWS * N2P];
__device__ __nv_bfloat16 g_w2hi[N2P * K1P];
__device__ __nv_bfloat16 g_w2lo[N2P * K1P];
__device__ __nv_bfloat16 g_w3hi[N3P * N2P];
__device__ __nv_bfloat16 g_w3lo[N3P * N2P];
__device__ __nv_bfloat16 g_t1hi[(size_t)M_ROWS * 16];
__device__ __nv_bfloat16 g_t1lo[(size_t)M_ROWS * 16];
__device__ __nv_bfloat16 g_t2hi[B_ROWS * 16];
__device__ __nv_bfloat16 g_t2lo[B_ROWS * 16];
__device__ int g_maxkey[B_ROWS];

// ---------- helpers ----------
__device__ __forceinline__ uint32_t smem_u32(const void* p) {
    uint32_t a;
    asm("{ .reg .u64 t; cvta.to.shared.u64 t, %1; cvt.u32.u64 %0, t; }" : "=r"(a) : "l"(p));
    return a;
}
__device__ __forceinline__ void cp16(uint32_t saddr, const void* gaddr) {
    asm volatile("cp.async.cg.shared.global [%0], [%1], 16;" :: "r"(saddr), "l"(gaddr));
}
#define CP_COMMIT() asm volatile("cp.async.commit_group;" ::: "memory")
#define CP_WAIT1()  asm volatile("cp.async.wait_group 1;" ::: "memory")
__device__ __forceinline__ void ldm_x4(uint32_t& r0, uint32_t& r1, uint32_t& r2,
                                       uint32_t& r3, uint32_t addr) {
    asm volatile("ldmatrix.sync.aligned.m8n8.x4.shared.b16 {%0,%1,%2,%3}, [%4];"
                 : "=r"(r0), "=r"(r1), "=r"(r2), "=r"(r3) : "r"(addr));
}
__device__ __forceinline__ void mma_bf16(float* c, const uint32_t* a,
                                         uint32_t b0, uint32_t b1) {
    asm volatile(
        "mma.sync.aligned.m16n8k16.row.col.f32.bf16.bf16.f32 "
        "{%0,%1,%2,%3}, {%4,%5,%6,%7}, {%8,%9}, {%0,%1,%2,%3};"
        : "+f"(c[0]), "+f"(c[1]), "+f"(c[2]), "+f"(c[3])
        : "r"(a[0]), "r"(a[1]), "r"(a[2]), "r"(a[3]), "r"(b0), "r"(b1));
}
__device__ __forceinline__ int fkey(float f) {
    int i = __float_as_int(f);
    return (i >= 0) ? i : (i ^ 0x7FFFFFFF);
}
__device__ __forceinline__ float finv(int k) {
    return __int_as_float((k >= 0) ? k : (k ^ 0x7FFFFFFF));
}
__device__ __forceinline__ void bsplit(float v, __nv_bfloat16& hi, __nv_bfloat16& lo) {
    hi = __float2bfloat16(v);
    lo = __float2bfloat16(v - __bfloat162float(hi));
}

// ============================================================
// k_head: merged k_l1 (blocks 0..1023) + prep/pre (blocks 1024..1039)
// ============================================================
#define L1_SMEM ((4200 + 300 + 64 * 304) * 4)
__global__ void __launch_bounds__(256)
k_head(const float* __restrict__ memory, const float* __restrict__ W1,
       const float* __restrict__ b1, const float* __restrict__ W2,
       const float* __restrict__ W3, const float* __restrict__ value) {
    extern __shared__ float sf[];
    const int t = threadIdx.x;

    if (blockIdx.x >= 1024) {
        const int pb = blockIdx.x - 1024;
        const int gid = pb * 256 + t;
        const int pstride = 16 * 256;
        for (int i = gid; i < N2P * K1P; i += pstride) {
            int n = i / K1P, k = i % K1P;
            float v = (n < 600 && k < 300) ? W2[n * 300 + k] : 0.f;
            __nv_bfloat16 h, l; bsplit(v, h, l);
            g_w2hi[i] = h; g_w2lo[i] = l;
        }
        for (int i = gid; i < N3P * N2P; i += pstride) {
            int c = i / N2P, k = i % N2P;
            float v = (c < 100 && k < 600) ? W3[c * 600 + k] : 0.f;
            __nv_bfloat16 h, l; bsplit(v, h, l);
            g_w3hi[i] = h; g_w3lo[i] = l;
        }
        if (gid < B_ROWS) {
            float v[DD]; float ss = 0.f;
#pragma unroll
            for (int d = 0; d < DD; d++) { v[d] = value[gid * DD + d]; ss += v[d] * v[d]; }
            float inv = 1.0f / fmaxf(sqrtf(ss), 1e-8f);
#pragma unroll
            for (int p = 0; p < 8; p++) {
                float v0 = (2 * p < DD) ? v[2 * p] * inv : 0.f;
                float v1 = (2 * p + 1 < DD) ? v[2 * p + 1] * inv : 0.f;
                __nv_bfloat16 h0, l0, h1, l1;
                bsplit(v0, h0, l0); bsplit(v1, h1, l1);
                __nv_bfloat162 vh; vh.x = h0; vh.y = h1;
                __nv_bfloat162 vl; vl.x = l0; vl.y = l1;
                *reinterpret_cast<__nv_bfloat162*>(g_t2hi + gid * 16 + 2 * p) = vh;
                *reinterpret_cast<__nv_bfloat162*>(g_t2lo + gid * 16 + 2 * p) = vl;
            }
            g_maxkey[gid] = fkey(-3.0e38f);
        }
        return;
    }

    const int row0 = blockIdx.x * 64;
    for (int i = t; i < 300 * DD; i += 256) { int k = i / DD, d = i % DD; sf[k * 14 + d] = W1[i]; }
    for (int i = t; i < 300; i += 256) sf[4200 + i] = b1[i];
    const int m = t & 63, kg = t >> 6;
    float x[DD];
#pragma unroll
    for (int d = 0; d < DD; d++) x[d] = memory[(row0 + m) * DD + d];
    __syncthreads();
    for (int k = kg * 75; k < kg * 75 + 75; k++) {
        const float* wr = sf + k * 14;
        float acc = sf[4200 + k];
#pragma unroll
        for (int d = 0; d < DD; d++) acc += x[d] * wr[d];
        sf[4500 + m * 304 + k] = fmaxf(acc, 0.f);
    }
    __syncthreads();
    for (int i = t; i < 64 * 160; i += 256) {
        int row = i / 160, kp = (i % 160) * 2;
        float v0 = (kp < 300) ? sf[4500 + row * 304 + kp] : 0.f;
        float v1 = (kp + 1 < 300) ? sf[4500 + row * 304 + kp + 1] : 0.f;
        __nv_bfloat16 h0, l0, h1, l1;
        bsplit(v0, h0, l0); bsplit(v1, h1, l1);
        __nv_bfloat162 ph; ph.x = h0; ph.y = h1;
        __nv_bfloat162 pl; pl.x = l0; pl.y = l1;
        size_t o = (size_t)(row0 + row) * K1P + kp;
        *reinterpret_cast<__nv_bfloat162*>(g_h1hi + o) = ph;
        *reinterpret_cast<__nv_bfloat162*>(g_h1lo + o) = pl;
    }
}

// ============================================================
// k_l2: warp split-K (unchanged from R12)
// ============================================================
#define STG2 16384
#define L2_SMEM (1024 + 3 * STG2)
__device__ __forceinline__ void l2_stage(uint32_t bufs, int t, int m0, int n0, int kc) {
#pragma unroll
    for (int ii = 0; ii < 4; ii++) {
        int i = t + ii * 256;
        int c16 = i & 3;
        int r = (i >> 2) & 63;
        int pl = (i >> 8) & 1;
        int sel = i >> 9;
        int phys = c16 ^ ((r >> 1) & 3);
        if (sel == 0) {
            const char* src = pl ? (const char*)g_h1lo : (const char*)g_h1hi;
            cp16(bufs + pl * 4096 + r * 64 + phys * 16,
                 src + ((size_t)(m0 + r) * K1P + kc + c16 * 8) * 2);
        } else {
            const char* src = pl ? (const char*)g_w2lo : (const char*)g_w2hi;
            cp16(bufs + 8192 + pl * 4096 + r * 64 + phys * 16,
                 src + ((size_t)(n0 + r) * K1P + kc + c16 * 8) * 2);
        }
    }
}

__global__ void __launch_bounds__(256, 3)
k_l2(const float* __restrict__ b2) {
    extern __shared__ char smc[];
    const uint32_t sb = smem_u32(smc);
    float* biasS = reinterpret_cast<float*>(smc);
    const int t = threadIdx.x, warp = t >> 5, lane = t & 31;
    const int n0 = blockIdx.x * 64, m0 = blockIdx.y * 64;
    const int wpos = warp & 3, wk = warp >> 2;
    const int m_warp = (wpos & 1) * 32, n_warp = (wpos >> 1) * 32;

    for (int i = t; i < 64; i += 256) { int j = n0 + i; biasS[i] = (j < 600) ? b2[j] : 0.f; }

    const int rA0 = m_warp + (lane & 7) + ((lane >> 3) & 1) * 8;
    const int cA  = lane >> 4;
    const int rB0 = n_warp + (lane & 7) + (lane >> 4) * 8;
    const int cB  = (lane >> 3) & 1;

    uint32_t offA[2], offB[2];
#pragma unroll
    for (int f = 0; f < 2; f++) {
        int rA = rA0 + f * 16;
        offA[f] = (uint32_t)(rA * 64 + (((cA + 2 * wk) ^ ((rA >> 1) & 3))) * 16);
        int rB = rB0 + f * 16;
        offB[f] = (uint32_t)(8192 + rB * 64 + (((cB + 2 * wk) ^ ((rB >> 1) & 3))) * 16);
    }

    float acc[2][4][4];
#pragma unroll
    for (int f = 0; f < 2; f++)
#pragma unroll
        for (int n = 0; n < 4; n++)
#pragma unroll
            for (int q = 0; q < 4; q++) acc[f][n][q] = 0.f;

    l2_stage(sb + 1024, t, m0, n0, 0); CP_COMMIT();
    l2_stage(sb + 1024 + STG2, t, m0, n0, 32); CP_COMMIT();

    for (int ch = 0; ch < 10; ch++) {
        CP_WAIT1();
        __syncthreads();
        if (ch + 2 < 10)
            l2_stage(sb + 1024 + ((ch + 2) % 3) * STG2, t, m0, n0, (ch + 2) * 32);
        CP_COMMIT();

        const uint32_t buf = sb + 1024 + (ch % 3) * STG2;
        uint32_t aH[2][4], aL[2][4], bH[2][4], bL[2][4];
#pragma unroll
        for (int f = 0; f < 2; f++) {
            uint32_t ad = buf + offA[f];
            ldm_x4(aH[f][0], aH[f][1], aH[f][2], aH[f][3], ad);
            ldm_x4(aL[f][0], aL[f][1], aL[f][2], aL[f][3], ad + 4096);
        }
#pragma unroll
        for (int bp = 0; bp < 2; bp++) {
            uint32_t bd = buf + offB[bp];
            ldm_x4(bH[bp][0], bH[bp][1], bH[bp][2], bH[bp][3], bd);
            ldm_x4(bL[bp][0], bL[bp][1], bL[bp][2], bL[bp][3], bd + 4096);
        }
#pragma unroll
        for (int bp = 0; bp < 2; bp++)
#pragma unroll
            for (int f = 0; f < 2; f++)
#pragma unroll
                for (int h = 0; h < 2; h++)
                    mma_bf16(acc[f][bp * 2 + h], aH[f], bH[bp][2 * h], bH[bp][2 * h + 1]);
#pragma unroll
        for (int bp = 0; bp < 2; bp++)
#pragma unroll
            for (int f = 0; f < 2; f++)
#pragma unroll
                for (int h = 0; h < 2; h++)
                    mma_bf16(acc[f][bp * 2 + h], aH[f], bL[bp][2 * h], bL[bp][2 * h + 1]);
#pragma unroll
        for (int bp = 0; bp < 2; bp++)
#pragma unroll
            for (int f = 0; f < 2; f++)
#pragma unroll
                for (int h = 0; h < 2; h++)
                    mma_bf16(acc[f][bp * 2 + h], aL[f], bH[bp][2 * h], bH[bp][2 * h + 1]);
    }
    __syncthreads();

    float* red = reinterpret_cast<float*>(smc + 1024);
    if (wk == 1) {
        const int col = wpos * 32 + lane;
#pragma unroll
        for (int f = 0; f < 2; f++)
#pragma unroll
            for (int nf = 0; nf < 4; nf++)
#pragma unroll
                for (int q = 0; q < 4; q++)
                    red[(f * 16 + nf * 4 + q) * 128 + col] = acc[f][nf][q];
    }
    __syncthreads();

#define L2_EHI 17408
#define L2_ELO 25600
    if (wk == 0) {
        const int col32 = wpos * 32 + lane;
#pragma unroll
        for (int f = 0; f < 2; f++) {
            int r0 = m_warp + f * 16 + (lane >> 2);
#pragma unroll
            for (int nf = 0; nf < 4; nf++) {
                int col = n_warp + nf * 8 + (lane & 3) * 2;
                float b0 = biasS[col], b1 = biasS[col + 1];
#pragma unroll
                for (int hrow = 0; hrow < 2; hrow++) {
                    int r = r0 + hrow * 8;
                    float z0 = acc[f][nf][2 * hrow]
                             + red[(f * 16 + nf * 4 + 2 * hrow) * 128 + col32] + b0;
                    float z1 = acc[f][nf][2 * hrow + 1]
                             + red[(f * 16 + nf * 4 + 2 * hrow + 1) * 128 + col32] + b1;
                    z0 = (z0 > 0.f) ? z0 : 0.01f * z0;
                    z1 = (z1 > 0.f) ? z1 : 0.01f * z1;
                    __nv_bfloat16 h0, l0, h1, l1;
                    bsplit(z0, h0, l0); bsplit(z1, h1, l1);
                    __nv_bfloat162 vh; vh.x = h0; vh.y = h1;
                    __nv_bfloat162 vl; vl.x = l0; vl.y = l1;
                    *reinterpret_cast<__nv_bfloat162*>(smc + L2_EHI + r * 128 + col * 2) = vh;
                    *reinterpret_cast<__nv_bfloat162*>(smc + L2_ELO + r * 128 + col * 2) = vl;
                }
            }
        }
    }
    __syncthreads();
    for (int i = t; i < 1024; i += 256) {
        int pl = i >> 9, r = (i >> 3) & 63, cc = i & 7;
        char* dst = pl ? (char*)g_h2lo : (char*)g_h2hi;
        *reinterpret_cast<float4*>(dst + ((size_t)(m0 + r) * N2P + n0) * 2 + cc * 16) =
            *reinterpret_cast<const float4*>(smc + (pl ? L2_ELO : L2_EHI) + r * 128 + cc * 16);
    }
}

// ============================================================
// k_l3: persistent grid 888, CTA 64m x 128n, K=608 (19 chunks;
// h2 cols 600..607 and W3 plane cols there are exactly zero).
// ============================================================
#define STG3 24576
#define L3_SMEM (1024 + 3 * STG3)
#define L3_GRID 888
#define L3_CHUNKS 19
__device__ __forceinline__ void l3_stage(uint32_t bufs, int t, int m0, int kc) {
#pragma unroll
    for (int ii = 0; ii < 6; ii++) {
        int i = t + ii * 256;
        int c16 = i & 3;
        if (i < 512) {
            int pl = i >> 8, r = (i >> 2) & 63;
            const char* src = pl ? (const char*)g_h2lo : (const char*)g_h2hi;
            int phys = c16 ^ ((r >> 1) & 3);
            cp16(bufs + pl * 4096 + r * 64 + phys * 16,
                 src + ((size_t)(m0 + r) * N2P + kc + c16 * 8) * 2);
        } else {
            int j = i - 512;
            int pl = j >> 9, r = (j >> 2) & 127;
            const char* src = pl ? (const char*)g_w3lo : (const char*)g_w3hi;
            int phys = c16 ^ ((r >> 1) & 3);
            cp16(bufs + 8192 + pl * 8192 + r * 64 + phys * 16,
                 src + ((size_t)r * N2P + kc + c16 * 8) * 2);
        }
    }
}

__global__ void __launch_bounds__(256, 3)
k_l3(const float* __restrict__ b3, const float* __restrict__ b4,
     const float* __restrict__ W4) {
    extern __shared__ char smc[];
    const uint32_t sb = smem_u32(smc);
    float* b3s = reinterpret_cast<float*>(smc);
    float* b4s = reinterpret_cast<float*>(smc + 512);
    const int t = threadIdx.x, warp = t >> 5, lane = t & 31;
    const int m_warp = (warp & 1) * 32, n_warp = (warp >> 1) * 32;

    for (int i = t; i < 128; i += 256) b3s[i] = (i < 100) ? b3[i] : 0.f;
    if (t < 16) b4s[t] = (t < DD) ? b4[t] : 0.f;

    const int rA0 = m_warp + (lane & 7) + ((lane >> 3) & 1) * 8;
    const int cA  = lane >> 4;
    const int rB0 = n_warp + (lane & 7) + (lane >> 4) * 8;
    const int cB  = (lane >> 3) & 1;

    uint32_t offA[2][2], offB[2][2];
#pragma unroll
    for (int f = 0; f < 2; f++)
#pragma unroll
        for (int ks = 0; ks < 2; ks++) {
            int rA = rA0 + f * 16;
            offA[f][ks] = (uint32_t)(rA * 64 + (((cA + 2 * ks) ^ ((rA >> 1) & 3))) * 16);
            int rB = rB0 + f * 16;
            offB[f][ks] = (uint32_t)(8192 + rB * 64 + (((cB + 2 * ks) ^ ((rB >> 1) & 3))) * 16);
        }

    for (int tile = blockIdx.x; tile < 1024; tile += L3_GRID) {
        const int m0 = tile * 64;

        float acc[2][4][4];
#pragma unroll
        for (int f = 0; f < 2; f++)
#pragma unroll
            for (int n = 0; n < 4; n++)
#pragma unroll
                for (int q = 0; q < 4; q++) acc[f][n][q] = 0.f;

        __syncthreads();
        l3_stage(sb + 1024, t, m0, 0); CP_COMMIT();
        l3_stage(sb + 1024 + STG3, t, m0, 32); CP_COMMIT();

        for (int ch = 0; ch < L3_CHUNKS; ch++) {
            CP_WAIT1();
            __syncthreads();
            if (ch + 2 < L3_CHUNKS)
                l3_stage(sb + 1024 + ((ch + 2) % 3) * STG3, t, m0, (ch + 2) * 32);
            CP_COMMIT();

            const uint32_t buf = sb + 1024 + (ch % 3) * STG3;
#pragma unroll
            for (int ks = 0; ks < 2; ks++) {
                uint32_t aH[2][4], aL[2][4], bH[2][4], bL[2][4];
#pragma unroll
                for (int f = 0; f < 2; f++) {
                    uint32_t ad = buf + offA[f][ks];
                    ldm_x4(aH[f][0], aH[f][1], aH[f][2], aH[f][3], ad);
                    ldm_x4(aL[f][0], aL[f][1], aL[f][2], aL[f][3], ad + 4096);
                }
#pragma unroll
                for (int bp = 0; bp < 2; bp++) {
                    uint32_t bd = buf + offB[bp][ks];
                    ldm_x4(bH[bp][0], bH[bp][1], bH[bp][2], bH[bp][3], bd);
                    ldm_x4(bL[bp][0], bL[bp][1], bL[bp][2], bL[bp][3], bd + 8192);
                }
#pragma unroll
                for (int bp = 0; bp < 2; bp++)
#pragma unroll
                    for (int f = 0; f < 2; f++)
#pragma unroll
                        for (int h = 0; h < 2; h++)
                            mma_bf16(acc[f][bp * 2 + h], aH[f], bH[bp][2 * h], bH[bp][2 * h + 1]);
#pragma unroll
                for (int bp = 0; bp < 2; bp++)
#pragma unroll
                    for (int f = 0; f < 2; f++)
#pragma unroll
                        for (int h = 0; h < 2; h++)
                            mma_bf16(acc[f][bp * 2 + h], aH[f], bL[bp][2 * h], bL[bp][2 * h + 1]);
#pragma unroll
                for (int bp = 0; bp < 2; bp++)
#pragma unroll
                    for (int f = 0; f < 2; f++)
#pragma unroll
                        for (int h = 0; h < 2; h++)
                            mma_bf16(acc[f][bp * 2 + h], aL[f], bH[bp][2 * h], bH[bp][2 * h + 1]);
            }
        }
        __syncthreads();

        float* h3 = reinterpret_cast<float*>(smc + 1024);
        float* W4s = reinterpret_cast<float*>(smc + 35072);
        float* sp  = reinterpret_cast<float*>(smc + 41472);
#pragma unroll
        for (int f = 0; f < 2; f++) {
            int r0 = m_warp + f * 16 + (lane >> 2);
#pragma unroll
            for (int nf = 0; nf < 4; nf++) {
                int col = n_warp + nf * 8 + (lane & 3) * 2;
                const float* c = acc[f][nf];
#pragma unroll
                for (int hrow = 0; hrow < 2; hrow++) {
                    int r = r0 + hrow * 8;
                    h3[r * 133 + col]     = fmaxf(c[2 * hrow] + b3s[col], 0.f);
                    h3[r * 133 + col + 1] = fmaxf(c[2 * hrow + 1] + b3s[col + 1], 0.f);
                }
            }
        }
        for (int i = t; i < 13 * 112; i += 256) {
            int d = i / 112, c = i % 112;
            W4s[i] = (c < 100) ? W4[d * 100 + c] : 0.f;
        }
        __syncthreads();

        {
            const int r = t & 63, g = t >> 6;
            const float* hr = h3 + r * 133 + g * 25;
            const float* wb = W4s + g * 25;
            float p[DD];
#pragma unroll
            for (int d = 0; d < DD; d++) p[d] = 0.f;
#pragma unroll 5
            for (int c = 0; c < 25; c++) {
                float h = hr[c];
#pragma unroll
                for (int d = 0; d < DD; d++) p[d] += h * wb[d * 112 + c];
            }
#pragma unroll
            for (int d = 0; d < DD; d++) sp[(r * 4 + g) * 14 + d] = p[d];
        }
        __syncthreads();

        if (t < 64) {
            float t1[DD];
            float ss = 0.f;
#pragma unroll
            for (int d = 0; d < DD; d++) {
                float s_ = b4s[d] + sp[(t * 4 + 0) * 14 + d] + sp[(t * 4 + 1) * 14 + d]
                         + sp[(t * 4 + 2) * 14 + d] + sp[(t * 4 + 3) * 14 + d];
                float v = (s_ > 0.f) ? s_ : 0.01f * s_;
                t1[d] = v;
                ss += v * v;
            }
            float inv = 1.0f / fmaxf(sqrtf(ss), 1e-8f);
            size_t row = (size_t)(m0 + t) * 16;
#pragma unroll
            for (int p = 0; p < 8; p++) {
                float v0 = (2 * p < DD) ? t1[2 * p] * inv : 0.f;
                float v1 = (2 * p + 1 < DD) ? t1[2 * p + 1] * inv : 0.f;
                __nv_bfloat16 h0, l0, h1, l1;
                bsplit(v0, h0, l0); bsplit(v1, h1, l1);
                __nv_bfloat162 vh; vh.x = h0; vh.y = h1;
                __nv_bfloat162 vl; vl.x = l0; vl.y = l1;
                *reinterpret_cast<__nv_bfloat162*>(g_t1hi + row + 2 * p) = vh;
                *reinterpret_cast<__nv_bfloat162*>(g_t1lo + row + 2 * p) = vl;
            }
        }
    }
}

// ============================================================
// k_sim_t v4: CTA = 256 b rows (warp = 32 rows, all 32 m-steps),
// grid (8, 32) = 256 blocks -> single wave at 3 CTAs/SM.
// Register double-buffer on B: step s+1's LDSM issues before
// step s's MMAs -> LDSM latency hidden under 12 MMAs.
// smem 48KB: sA hi @0 (8K), lo @8192; sB hi @16384 (16K), lo @32768.
// ============================================================
__global__ void __launch_bounds__(256, 3) k_sim_t() {
    __shared__ char sm[49152];
    const uint32_t sb = smem_u32(sm);
    const int t = threadIdx.x, warp = t >> 5, lane = t & 31;
    const int b0 = blockIdx.x * 256;
    const int mbase = blockIdx.y * 2048;

    // stage t2 split block (256 rows x 2 planes), once
    for (int i = t; i < 1024; i += 256) {
        int pl = i >> 9, j = i & 511, row = j >> 1, half = j & 1;
        const char* src = pl ? (const char*)g_t2lo : (const char*)g_t2hi;
        int ph = half ^ ((row >> 2) & 1);
        *reinterpret_cast<float4*>(sm + pl * 8192 + row * 32 + ph * 16) =
            *reinterpret_cast<const float4*>(src + ((size_t)(b0 + row) * 16 + half * 8) * 2);
    }
    __syncthreads();

    // A fragments: 2 pairs covering this warp's 32 b rows, loaded once
    uint32_t aH[2][4], aL[2][4];
    const int cA = lane >> 4;
#pragma unroll
    for (int g = 0; g < 2; g++) {
        int rA = warp * 32 + g * 16 + (lane & 7) + ((lane >> 3) & 1) * 8;
        uint32_t aAddr = sb + rA * 32 + ((cA ^ ((rA >> 2) & 1))) * 16;
        ldm_x4(aH[g][0], aH[g][1], aH[g][2], aH[g][3], aAddr);
        ldm_x4(aL[g][0], aL[g][1], aL[g][2], aL[g][3], aAddr + 8192);
    }

    // B base: swizzle bit (rB>>2)&1 invariant under +16 row steps
    const int rB = (lane & 7) + (lane >> 4) * 8;
    const int cB = (lane >> 3) & 1;
    const uint32_t bBase = (uint32_t)(16384 + rB * 32 + ((cB ^ ((rB >> 2) & 1))) * 16);

    float mx[2][2];
#pragma unroll
    for (int g = 0; g < 2; g++) { mx[g][0] = -3.0e38f; mx[g][1] = -3.0e38f; }

    for (int c = 0; c < 4; c++) {
        __syncthreads();
        for (int i = t; i < 2048; i += 256) {
            int pl = i >> 10, j = i & 1023, row = j >> 1, half = j & 1;
            const char* src = pl ? (const char*)g_t1lo : (const char*)g_t1hi;
            int ph = half ^ ((row >> 2) & 1);
            *reinterpret_cast<float4*>(sm + 16384 + pl * 16384 + row * 32 + ph * 16) =
                *reinterpret_cast<const float4*>(
                    src + ((size_t)(mbase + c * 512 + row) * 16 + half * 8) * 2);
        }
        __syncthreads();

        uint32_t bAddr = sb + bBase;
        uint32_t bHa[4], bLa[4], bHb[4], bLb[4];
        ldm_x4(bHa[0], bHa[1], bHa[2], bHa[3], bAddr);
        ldm_x4(bLa[0], bLa[1], bLa[2], bLa[3], bAddr + 16384);

#pragma unroll 2
        for (int s = 0; s < 32; s += 2) {
            // prefetch step s+1
            ldm_x4(bHb[0], bHb[1], bHb[2], bHb[3], bAddr + 512);
            ldm_x4(bLb[0], bLb[1], bLb[2], bLb[3], bAddr + 512 + 16384);
            // compute step s with bHa/bLa
#pragma unroll
            for (int g = 0; g < 2; g++) {
                float a0[4] = {0.f, 0.f, 0.f, 0.f};
                float a1[4] = {0.f, 0.f, 0.f, 0.f};
                mma_bf16(a0, aH[g], bHa[0], bHa[1]);
                mma_bf16(a1, aH[g], bHa[2], bHa[3]);
                mma_bf16(a0, aH[g], bLa[0], bLa[1]);
                mma_bf16(a1, aH[g], bLa[2], bLa[3]);
                mma_bf16(a0, aL[g], bHa[0], bHa[1]);
                mma_bf16(a1, aL[g], bHa[2], bHa[3]);
                mx[g][0] = fmaxf(mx[g][0], fmaxf(fmaxf(a0[0], a0[1]), fmaxf(a1[0], a1[1])));
                mx[g][1] = fmaxf(mx[g][1], fmaxf(fmaxf(a0[2], a0[3]), fmaxf(a1[2], a1[3])));
            }
            // prefetch step s+2
            if (s + 2 < 32) {
                ldm_x4(bHa[0], bHa[1], bHa[2], bHa[3], bAddr + 1024);
                ldm_x4(bLa[0], bLa[1], bLa[2], bLa[3], bAddr + 1024 + 16384);
            }
            // compute step s+1 with bHb/bLb
#pragma unroll
            for (int g = 0; g < 2; g++) {
                float a0[4] = {0.f, 0.f, 0.f, 0.f};
                float a1[4] = {0.f, 0.f, 0.f, 0.f};
                mma_bf16(a0, aH[g], bHb[0], bHb[1]);
                mma_bf16(a1, aH[g], bHb[2], bHb[3]);
                mma_bf16(a0, aH[g], bLb[0], bLb[1]);
                mma_bf16(a1, aH[g], bLb[2], bLb[3]);
                mma_bf16(a0, aL[g], bHb[0], bHb[1]);
                mma_bf16(a1, aL[g], bHb[2], bHb[3]);
                mx[g][0] = fmaxf(mx[g][0], fmaxf(fmaxf(a0[0], a0[1]), fmaxf(a1[0], a1[1])));
                mx[g][1] = fmaxf(mx[g][1], fmaxf(fmaxf(a0[2], a0[3]), fmaxf(a1[2], a1[3])));
            }
            bAddr += 1024;
        }
    }

    // reduce across the 4 col-lanes sharing each row, then atomicMax
#pragma unroll
    for (int g = 0; g < 2; g++) {
        mx[g][0] = fmaxf(mx[g][0], __shfl_xor_sync(0xFFFFFFFF, mx[g][0], 1));
        mx[g][0] = fmaxf(mx[g][0], __shfl_xor_sync(0xFFFFFFFF, mx[g][0], 2));
        mx[g][1] = fmaxf(mx[g][1], __shfl_xor_sync(0xFFFFFFFF, mx[g][1], 1));
        mx[g][1] = fmaxf(mx[g][1], __shfl_xor_sync(0xFFFFFFFF, mx[g][1], 2));
    }
    if ((lane & 3) == 0) {
        const int base = b0 + warp * 32 + (lane >> 2);
#pragma unroll
        for (int g = 0; g < 2; g++) {
            atomicMax(&g_maxkey[base + g * 16], fkey(mx[g][0]));
            atomicMax(&g_maxkey[base + g * 16 + 8], fkey(mx[g][1]));
        }
    }
}

// ============================================================
__global__ void k_fin(float* __restrict__ out) {
    int b = blockIdx.x * blockDim.x + threadIdx.x;
    if (b < B_ROWS) out[b] = 23.0f * finv(g_maxkey[b]);
}

// ============================================================
extern "C" void kernel_launch(void* const* d_in, const int* in_sizes, int n_in,
                              void* d_out, int out_size) {
    const float* memory = (const float*)d_in[0];
    const float* value  = (const float*)d_in[1];
    const float* W1 = (const float*)d_in[2];
    const float* b1 = (const float*)d_in[3];
    const float* W2 = (const float*)d_in[4];
    const float* b2 = (const float*)d_in[5];
    const float* W3 = (const float*)d_in[6];
    const float* b3 = (const float*)d_in[7];
    const float* W4 = (const float*)d_in[8];
    const float* b4 = (const float*)d_in[9];

    cudaFuncSetAttribute(k_head, cudaFuncAttributeMaxDynamicSharedMemorySize, L1_SMEM);
    cudaFuncSetAttribute(k_l2, cudaFuncAttributeMaxDynamicSharedMemorySize, L2_SMEM);
    cudaFuncSetAttribute(k_l3, cudaFuncAttributeMaxDynamicSharedMemorySize, L3_SMEM);

    k_head<<<1040, 256, L1_SMEM>>>(memory, W1, b1, W2, W3, value);
    k_l2<<<dim3(10, 1024), 256, L2_SMEM>>>(b2);
    k_l3<<<L3_GRID, 256, L3_SMEM>>>(b3, b4, W4);
    k_sim_t<<<dim3(8, 32), 256>>>();
    k_fin<<<8, 256>>>((float*)d_out);
}

// round 16
// speedup vs baseline: 1.0124x; 1.0025x over previous
#include <cuda_runtime.h>
#include <cuda_bf16.h>
#include <cstdint>

#define M_ROWS 65536
#define B_ROWS 2048
#define DD 13
#define K1P 320
#define N2P 640
#define N3P 128

// ---------- global scratch ----------
__device__ __nv_bfloat16 g_h1hi[(size_t)M_ROWS * K1P];
__device__ __nv_bfloat16 g_h1lo[(size_t)M_ROWS * K1P];
__device__ __nv_bfloat16 g_h2hi[(size_t)M_ROWS * N2P];
__device__ __nv_bfloat16 g_h2lo[(size_t)M_ROWS * N2P];
__device__ __nv_bfloat16 g_w2hi[N2P * K1P];
__device__ __nv_bfloat16 g_w2lo[N2P * K1P];
__device__ __nv_bfloat16 g_w3hi[N3P * N2P];
__device__ __nv_bfloat16 g_w3lo[N3P * N2P];
__device__ __nv_bfloat16 g_t1hi[(size_t)M_ROWS * 16];
__device__ __nv_bfloat16 g_t1lo[(size_t)M_ROWS * 16];
__device__ __nv_bfloat16 g_t2hi[B_ROWS * 16];
__device__ __nv_bfloat16 g_t2lo[B_ROWS * 16];
__device__ int g_maxkey[B_ROWS];

// ---------- helpers ----------
__device__ __forceinline__ uint32_t smem_u32(const void* p) {
    uint32_t a;
    asm("{ .reg .u64 t; cvta.to.shared.u64 t, %1; cvt.u32.u64 %0, t; }" : "=r"(a) : "l"(p));
    return a;
}
__device__ __forceinline__ void cp16(uint32_t saddr, const void* gaddr) {
    asm volatile("cp.async.cg.shared.global [%0], [%1], 16;" :: "r"(saddr), "l"(gaddr));
}
#define CP_COMMIT() asm volatile("cp.async.commit_group;" ::: "memory")
#define CP_WAIT1()  asm volatile("cp.async.wait_group 1;" ::: "memory")
__device__ __forceinline__ void ldm_x4(uint32_t& r0, uint32_t& r1, uint32_t& r2,
                                       uint32_t& r3, uint32_t addr) {
    asm volatile("ldmatrix.sync.aligned.m8n8.x4.shared.b16 {%0,%1,%2,%3}, [%4];"
                 : "=r"(r0), "=r"(r1), "=r"(r2), "=r"(r3) : "r"(addr));
}
__device__ __forceinline__ void mma_bf16(float* c, const uint32_t* a,
                                         uint32_t b0, uint32_t b1) {
    asm volatile(
        "mma.sync.aligned.m16n8k16.row.col.f32.bf16.bf16.f32 "
        "{%0,%1,%2,%3}, {%4,%5,%6,%7}, {%8,%9}, {%0,%1,%2,%3};"
        : "+f"(c[0]), "+f"(c[1]), "+f"(c[2]), "+f"(c[3])
        : "r"(a[0]), "r"(a[1]), "r"(a[2]), "r"(a[3]), "r"(b0), "r"(b1));
}
__device__ __forceinline__ int fkey(float f) {
    int i = __float_as_int(f);
    return (i >= 0) ? i : (i ^ 0x7FFFFFFF);
}
__device__ __forceinline__ float finv(int k) {
    return __int_as_float((k >= 0) ? k : (k ^ 0x7FFFFFFF));
}
__device__ __forceinline__ void bsplit(float v, __nv_bfloat16& hi, __nv_bfloat16& lo) {
    hi = __float2bfloat16(v);
    lo = __float2bfloat16(v - __bfloat162float(hi));
}

// ============================================================
// k_head: merged k_l1 (blocks 0..1023) + prep/pre (blocks 1024..1039)
// ============================================================
#define L1_SMEM ((4200 + 300 + 64 * 304) * 4)
__global__ void __launch_bounds__(256)
k_head(const float* __restrict__ memory, const float* __restrict__ W1,
       const float* __restrict__ b1, const float* __restrict__ W2,
       const float* __restrict__ W3, const float* __restrict__ value) {
    extern __shared__ float sf[];
    const int t = threadIdx.x;

    if (blockIdx.x >= 1024) {
        const int pb = blockIdx.x - 1024;
        const int gid = pb * 256 + t;
        const int pstride = 16 * 256;
        for (int i = gid; i < N2P * K1P; i += pstride) {
            int n = i / K1P, k = i % K1P;
            float v = (n < 600 && k < 300) ? W2[n * 300 + k] : 0.f;
            __nv_bfloat16 h, l; bsplit(v, h, l);
            g_w2hi[i] = h; g_w2lo[i] = l;
        }
        for (int i = gid; i < N3P * N2P; i += pstride) {
            int c = i / N2P, k = i % N2P;
            float v = (c < 100 && k < 600) ? W3[c * 600 + k] : 0.f;
            __nv_bfloat16 h, l; bsplit(v, h, l);
            g_w3hi[i] = h; g_w3lo[i] = l;
        }
        if (gid < B_ROWS) {
            float v[DD]; float ss = 0.f;
#pragma unroll
            for (int d = 0; d < DD; d++) { v[d] = value[gid * DD + d]; ss += v[d] * v[d]; }
            float inv = 1.0f / fmaxf(sqrtf(ss), 1e-8f);
#pragma unroll
            for (int p = 0; p < 8; p++) {
                float v0 = (2 * p < DD) ? v[2 * p] * inv : 0.f;
                float v1 = (2 * p + 1 < DD) ? v[2 * p + 1] * inv : 0.f;
                __nv_bfloat16 h0, l0, h1, l1;
                bsplit(v0, h0, l0); bsplit(v1, h1, l1);
                __nv_bfloat162 vh; vh.x = h0; vh.y = h1;
                __nv_bfloat162 vl; vl.x = l0; vl.y = l1;
                *reinterpret_cast<__nv_bfloat162*>(g_t2hi + gid * 16 + 2 * p) = vh;
                *reinterpret_cast<__nv_bfloat162*>(g_t2lo + gid * 16 + 2 * p) = vl;
            }
            g_maxkey[gid] = fkey(-3.0e38f);
        }
        return;
    }

    const int row0 = blockIdx.x * 64;
    for (int i = t; i < 300 * DD; i += 256) { int k = i / DD, d = i % DD; sf[k * 14 + d] = W1[i]; }
    for (int i = t; i < 300; i += 256) sf[4200 + i] = b1[i];
    const int m = t & 63, kg = t >> 6;
    float x[DD];
#pragma unroll
    for (int d = 0; d < DD; d++) x[d] = memory[(row0 + m) * DD + d];
    __syncthreads();
    for (int k = kg * 75; k < kg * 75 + 75; k++) {
        const float* wr = sf + k * 14;
        float acc = sf[4200 + k];
#pragma unroll
        for (int d = 0; d < DD; d++) acc += x[d] * wr[d];
        sf[4500 + m * 304 + k] = fmaxf(acc, 0.f);
    }
    __syncthreads();
    for (int i = t; i < 64 * 160; i += 256) {
        int row = i / 160, kp = (i % 160) * 2;
        float v0 = (kp < 300) ? sf[4500 + row * 304 + kp] : 0.f;
        float v1 = (kp + 1 < 300) ? sf[4500 + row * 304 + kp + 1] : 0.f;
        __nv_bfloat16 h0, l0, h1, l1;
        bsplit(v0, h0, l0); bsplit(v1, h1, l1);
        __nv_bfloat162 ph; ph.x = h0; ph.y = h1;
        __nv_bfloat162 pl; pl.x = l0; pl.y = l1;
        size_t o = (size_t)(row0 + row) * K1P + kp;
        *reinterpret_cast<__nv_bfloat162*>(g_h1hi + o) = ph;
        *reinterpret_cast<__nv_bfloat162*>(g_h1lo + o) = pl;
    }
}

// ============================================================
// k_l2: warp split-K (unchanged from R12)
// ============================================================
#define STG2 16384
#define L2_SMEM (1024 + 3 * STG2)
__device__ __forceinline__ void l2_stage(uint32_t bufs, int t, int m0, int n0, int kc) {
#pragma unroll
    for (int ii = 0; ii < 4; ii++) {
        int i = t + ii * 256;
        int c16 = i & 3;
        int r = (i >> 2) & 63;
        int pl = (i >> 8) & 1;
        int sel = i >> 9;
        int phys = c16 ^ ((r >> 1) & 3);
        if (sel == 0) {
            const char* src = pl ? (const char*)g_h1lo : (const char*)g_h1hi;
            cp16(bufs + pl * 4096 + r * 64 + phys * 16,
                 src + ((size_t)(m0 + r) * K1P + kc + c16 * 8) * 2);
        } else {
            const char* src = pl ? (const char*)g_w2lo : (const char*)g_w2hi;
            cp16(bufs + 8192 + pl * 4096 + r * 64 + phys * 16,
                 src + ((size_t)(n0 + r) * K1P + kc + c16 * 8) * 2);
        }
    }
}

__global__ void __launch_bounds__(256, 3)
k_l2(const float* __restrict__ b2) {
    extern __shared__ char smc[];
    const uint32_t sb = smem_u32(smc);
    float* biasS = reinterpret_cast<float*>(smc);
    const int t = threadIdx.x, warp = t >> 5, lane = t & 31;
    const int n0 = blockIdx.x * 64, m0 = blockIdx.y * 64;
    const int wpos = warp & 3, wk = warp >> 2;
    const int m_warp = (wpos & 1) * 32, n_warp = (wpos >> 1) * 32;

    for (int i = t; i < 64; i += 256) { int j = n0 + i; biasS[i] = (j < 600) ? b2[j] : 0.f; }

    const int rA0 = m_warp + (lane & 7) + ((lane >> 3) & 1) * 8;
    const int cA  = lane >> 4;
    const int rB0 = n_warp + (lane & 7) + (lane >> 4) * 8;
    const int cB  = (lane >> 3) & 1;

    uint32_t offA[2], offB[2];
#pragma unroll
    for (int f = 0; f < 2; f++) {
        int rA = rA0 + f * 16;
        offA[f] = (uint32_t)(rA * 64 + (((cA + 2 * wk) ^ ((rA >> 1) & 3))) * 16);
        int rB = rB0 + f * 16;
        offB[f] = (uint32_t)(8192 + rB * 64 + (((cB + 2 * wk) ^ ((rB >> 1) & 3))) * 16);
    }

    float acc[2][4][4];
#pragma unroll
    for (int f = 0; f < 2; f++)
#pragma unroll
        for (int n = 0; n < 4; n++)
#pragma unroll
            for (int q = 0; q < 4; q++) acc[f][n][q] = 0.f;

    l2_stage(sb + 1024, t, m0, n0, 0); CP_COMMIT();
    l2_stage(sb + 1024 + STG2, t, m0, n0, 32); CP_COMMIT();

    for (int ch = 0; ch < 10; ch++) {
        CP_WAIT1();
        __syncthreads();
        if (ch + 2 < 10)
            l2_stage(sb + 1024 + ((ch + 2) % 3) * STG2, t, m0, n0, (ch + 2) * 32);
        CP_COMMIT();

        const uint32_t buf = sb + 1024 + (ch % 3) * STG2;
        uint32_t aH[2][4], aL[2][4], bH[2][4], bL[2][4];
#pragma unroll
        for (int f = 0; f < 2; f++) {
            uint32_t ad = buf + offA[f];
            ldm_x4(aH[f][0], aH[f][1], aH[f][2], aH[f][3], ad);
            ldm_x4(aL[f][0], aL[f][1], aL[f][2], aL[f][3], ad + 4096);
        }
#pragma unroll
        for (int bp = 0; bp < 2; bp++) {
            uint32_t bd = buf + offB[bp];
            ldm_x4(bH[bp][0], bH[bp][1], bH[bp][2], bH[bp][3], bd);
            ldm_x4(bL[bp][0], bL[bp][1], bL[bp][2], bL[bp][3], bd + 4096);
        }
#pragma unroll
        for (int bp = 0; bp < 2; bp++)
#pragma unroll
            for (int f = 0; f < 2; f++)
#pragma unroll
                for (int h = 0; h < 2; h++)
                    mma_bf16(acc[f][bp * 2 + h], aH[f], bH[bp][2 * h], bH[bp][2 * h + 1]);
#pragma unroll
        for (int bp = 0; bp < 2; bp++)
#pragma unroll
            for (int f = 0; f < 2; f++)
#pragma unroll
                for (int h = 0; h < 2; h++)
                    mma_bf16(acc[f][bp * 2 + h], aH[f], bL[bp][2 * h], bL[bp][2 * h + 1]);
#pragma unroll
        for (int bp = 0; bp < 2; bp++)
#pragma unroll
            for (int f = 0; f < 2; f++)
#pragma unroll
                for (int h = 0; h < 2; h++)
                    mma_bf16(acc[f][bp * 2 + h], aL[f], bH[bp][2 * h], bH[bp][2 * h + 1]);
    }
    __syncthreads();

    float* red = reinterpret_cast<float*>(smc + 1024);
    if (wk == 1) {
        const int col = wpos * 32 + lane;
#pragma unroll
        for (int f = 0; f < 2; f++)
#pragma unroll
            for (int nf = 0; nf < 4; nf++)
#pragma unroll
                for (int q = 0; q < 4; q++)
                    red[(f * 16 + nf * 4 + q) * 128 + col] = acc[f][nf][q];
    }
    __syncthreads();

#define L2_EHI 17408
#define L2_ELO 25600
    if (wk == 0) {
        const int col32 = wpos * 32 + lane;
#pragma unroll
        for (int f = 0; f < 2; f++) {
            int r0 = m_warp + f * 16 + (lane >> 2);
#pragma unroll
            for (int nf = 0; nf < 4; nf++) {
                int col = n_warp + nf * 8 + (lane & 3) * 2;
                float b0 = biasS[col], b1 = biasS[col + 1];
#pragma unroll
                for (int hrow = 0; hrow < 2; hrow++) {
                    int r = r0 + hrow * 8;
                    float z0 = acc[f][nf][2 * hrow]
                             + red[(f * 16 + nf * 4 + 2 * hrow) * 128 + col32] + b0;
                    float z1 = acc[f][nf][2 * hrow + 1]
                             + red[(f * 16 + nf * 4 + 2 * hrow + 1) * 128 + col32] + b1;
                    z0 = (z0 > 0.f) ? z0 : 0.01f * z0;
                    z1 = (z1 > 0.f) ? z1 : 0.01f * z1;
                    __nv_bfloat16 h0, l0, h1, l1;
                    bsplit(z0, h0, l0); bsplit(z1, h1, l1);
                    __nv_bfloat162 vh; vh.x = h0; vh.y = h1;
                    __nv_bfloat162 vl; vl.x = l0; vl.y = l1;
                    *reinterpret_cast<__nv_bfloat162*>(smc + L2_EHI + r * 128 + col * 2) = vh;
                    *reinterpret_cast<__nv_bfloat162*>(smc + L2_ELO + r * 128 + col * 2) = vl;
                }
            }
        }
    }
    __syncthreads();
    for (int i = t; i < 1024; i += 256) {
        int pl = i >> 9, r = (i >> 3) & 63, cc = i & 7;
        char* dst = pl ? (char*)g_h2lo : (char*)g_h2hi;
        *reinterpret_cast<float4*>(dst + ((size_t)(m0 + r) * N2P + n0) * 2 + cc * 16) =
            *reinterpret_cast<const float4*>(smc + (pl ? L2_ELO : L2_EHI) + r * 128 + cc * 16);
    }
}

// ============================================================
// k_l3: persistent grid 888, CTA 64m x 128n, K=608 (19 chunks;
// h2 cols 600..607 and W3 plane cols there are exactly zero).
// ============================================================
#define STG3 24576
#define L3_SMEM (1024 + 3 * STG3)
#define L3_GRID 888
#define L3_CHUNKS 19
__device__ __forceinline__ void l3_stage(uint32_t bufs, int t, int m0, int kc) {
#pragma unroll
    for (int ii = 0; ii < 6; ii++) {
        int i = t + ii * 256;
        int c16 = i & 3;
        if (i < 512) {
            int pl = i >> 8, r = (i >> 2) & 63;
            const char* src = pl ? (const char*)g_h2lo : (const char*)g_h2hi;
            int phys = c16 ^ ((r >> 1) & 3);
            cp16(bufs + pl * 4096 + r * 64 + phys * 16,
                 src + ((size_t)(m0 + r) * N2P + kc + c16 * 8) * 2);
        } else {
            int j = i - 512;
            int pl = j >> 9, r = (j >> 2) & 127;
            const char* src = pl ? (const char*)g_w3lo : (const char*)g_w3hi;
            int phys = c16 ^ ((r >> 1) & 3);
            cp16(bufs + 8192 + pl * 8192 + r * 64 + phys * 16,
                 src + ((size_t)r * N2P + kc + c16 * 8) * 2);
        }
    }
}

__global__ void __launch_bounds__(256, 3)
k_l3(const float* __restrict__ b3, const float* __restrict__ b4,
     const float* __restrict__ W4) {
    extern __shared__ char smc[];
    const uint32_t sb = smem_u32(smc);
    float* b3s = reinterpret_cast<float*>(smc);
    float* b4s = reinterpret_cast<float*>(smc + 512);
    const int t = threadIdx.x, warp = t >> 5, lane = t & 31;
    const int m_warp = (warp & 1) * 32, n_warp = (warp >> 1) * 32;

    for (int i = t; i < 128; i += 256) b3s[i] = (i < 100) ? b3[i] : 0.f;
    if (t < 16) b4s[t] = (t < DD) ? b4[t] : 0.f;

    const int rA0 = m_warp + (lane & 7) + ((lane >> 3) & 1) * 8;
    const int cA  = lane >> 4;
    const int rB0 = n_warp + (lane & 7) + (lane >> 4) * 8;
    const int cB  = (lane >> 3) & 1;

    uint32_t offA[2][2], offB[2][2];
#pragma unroll
    for (int f = 0; f < 2; f++)
#pragma unroll
        for (int ks = 0; ks < 2; ks++) {
            int rA = rA0 + f * 16;
            offA[f][ks] = (uint32_t)(rA * 64 + (((cA + 2 * ks) ^ ((rA >> 1) & 3))) * 16);
            int rB = rB0 + f * 16;
            offB[f][ks] = (uint32_t)(8192 + rB * 64 + (((cB + 2 * ks) ^ ((rB >> 1) & 3))) * 16);
        }

    for (int tile = blockIdx.x; tile < 1024; tile += L3_GRID) {
        const int m0 = tile * 64;

        float acc[2][4][4];
#pragma unroll
        for (int f = 0; f < 2; f++)
#pragma unroll
            for (int n = 0; n < 4; n++)
#pragma unroll
                for (int q = 0; q < 4; q++) acc[f][n][q] = 0.f;

        __syncthreads();
        l3_stage(sb + 1024, t, m0, 0); CP_COMMIT();
        l3_stage(sb + 1024 + STG3, t, m0, 32); CP_COMMIT();

        for (int ch = 0; ch < L3_CHUNKS; ch++) {
            CP_WAIT1();
            __syncthreads();
            if (ch + 2 < L3_CHUNKS)
                l3_stage(sb + 1024 + ((ch + 2) % 3) * STG3, t, m0, (ch + 2) * 32);
            CP_COMMIT();

            const uint32_t buf = sb + 1024 + (ch % 3) * STG3;
#pragma unroll
            for (int ks = 0; ks < 2; ks++) {
                uint32_t aH[2][4], aL[2][4], bH[2][4], bL[2][4];
#pragma unroll
                for (int f = 0; f < 2; f++) {
                    uint32_t ad = buf + offA[f][ks];
                    ldm_x4(aH[f][0], aH[f][1], aH[f][2], aH[f][3], ad);
                    ldm_x4(aL[f][0], aL[f][1], aL[f][2], aL[f][3], ad + 4096);
                }
#pragma unroll
                for (int bp = 0; bp < 2; bp++) {
                    uint32_t bd = buf + offB[bp][ks];
                    ldm_x4(bH[bp][0], bH[bp][1], bH[bp][2], bH[bp][3], bd);
                    ldm_x4(bL[bp][0], bL[bp][1], bL[bp][2], bL[bp][3], bd + 8192);
                }
#pragma unroll
                for (int bp = 0; bp < 2; bp++)
#pragma unroll
                    for (int f = 0; f < 2; f++)
#pragma unroll
                        for (int h = 0; h < 2; h++)
                            mma_bf16(acc[f][bp * 2 + h], aH[f], bH[bp][2 * h], bH[bp][2 * h + 1]);
#pragma unroll
                for (int bp = 0; bp < 2; bp++)
#pragma unroll
                    for (int f = 0; f < 2; f++)
#pragma unroll
                        for (int h = 0; h < 2; h++)
                            mma_bf16(acc[f][bp * 2 + h], aH[f], bL[bp][2 * h], bL[bp][2 * h + 1]);
#pragma unroll
                for (int bp = 0; bp < 2; bp++)
#pragma unroll
                    for (int f = 0; f < 2; f++)
#pragma unroll
                        for (int h = 0; h < 2; h++)
                            mma_bf16(acc[f][bp * 2 + h], aL[f], bH[bp][2 * h], bH[bp][2 * h + 1]);
            }
        }
        __syncthreads();

        float* h3 = reinterpret_cast<float*>(smc + 1024);
        float* W4s = reinterpret_cast<float*>(smc + 35072);
        float* sp  = reinterpret_cast<float*>(smc + 41472);
#pragma unroll
        for (int f = 0; f < 2; f++) {
            int r0 = m_warp + f * 16 + (lane >> 2);
#pragma unroll
            for (int nf = 0; nf < 4; nf++) {
                int col = n_warp + nf * 8 + (lane & 3) * 2;
                const float* c = acc[f][nf];
#pragma unroll
                for (int hrow = 0; hrow < 2; hrow++) {
                    int r = r0 + hrow * 8;
                    h3[r * 133 + col]     = fmaxf(c[2 * hrow] + b3s[col], 0.f);
                    h3[r * 133 + col + 1] = fmaxf(c[2 * hrow + 1] + b3s[col + 1], 0.f);
                }
            }
        }
        for (int i = t; i < 13 * 112; i += 256) {
            int d = i / 112, c = i % 112;
            W4s[i] = (c < 100) ? W4[d * 100 + c] : 0.f;
        }
        __syncthreads();

        {
            const int r = t & 63, g = t >> 6;
            const float* hr = h3 + r * 133 + g * 25;
            const float* wb = W4s + g * 25;
            float p[DD];
#pragma unroll
            for (int d = 0; d < DD; d++) p[d] = 0.f;
#pragma unroll 5
            for (int c = 0; c < 25; c++) {
                float h = hr[c];
#pragma unroll
                for (int d = 0; d < DD; d++) p[d] += h * wb[d * 112 + c];
            }
#pragma unroll
            for (int d = 0; d < DD; d++) sp[(r * 4 + g) * 14 + d] = p[d];
        }
        __syncthreads();

        if (t < 64) {
            float t1[DD];
            float ss = 0.f;
#pragma unroll
            for (int d = 0; d < DD; d++) {
                float s_ = b4s[d] + sp[(t * 4 + 0) * 14 + d] + sp[(t * 4 + 1) * 14 + d]
                         + sp[(t * 4 + 2) * 14 + d] + sp[(t * 4 + 3) * 14 + d];
                float v = (s_ > 0.f) ? s_ : 0.01f * s_;
                t1[d] = v;
                ss += v * v;
            }
            float inv = 1.0f / fmaxf(sqrtf(ss), 1e-8f);
            size_t row = (size_t)(m0 + t) * 16;
#pragma unroll
            for (int p = 0; p < 8; p++) {
                float v0 = (2 * p < DD) ? t1[2 * p] * inv : 0.f;
                float v1 = (2 * p + 1 < DD) ? t1[2 * p + 1] * inv : 0.f;
                __nv_bfloat16 h0, l0, h1, l1;
                bsplit(v0, h0, l0); bsplit(v1, h1, l1);
                __nv_bfloat162 vh; vh.x = h0; vh.y = h1;
                __nv_bfloat162 vl; vl.x = l0; vl.y = l1;
                *reinterpret_cast<__nv_bfloat162*>(g_t1hi + row + 2 * p) = vh;
                *reinterpret_cast<__nv_bfloat162*>(g_t1lo + row + 2 * p) = vl;
            }
        }
    }
}

// ============================================================
// k_sim_t v4: CTA = 256 b rows (warp = 32 rows, all 32 m-steps),
// grid (8, 32) = 256 blocks -> single wave at 3 CTAs/SM.
// Register double-buffer on B: step s+1's LDSM issues before
// step s's MMAs -> LDSM latency hidden under 12 MMAs.
// smem 48KB: sA hi @0 (8K), lo @8192; sB hi @16384 (16K), lo @32768.
// ============================================================
__global__ void __launch_bounds__(256, 3) k_sim_t() {
    __shared__ char sm[49152];
    const uint32_t sb = smem_u32(sm);
    const int t = threadIdx.x, warp = t >> 5, lane = t & 31;
    const int b0 = blockIdx.x * 256;
    const int mbase = blockIdx.y * 2048;

    // stage t2 split block (256 rows x 2 planes), once
    for (int i = t; i < 1024; i += 256) {
        int pl = i >> 9, j = i & 511, row = j >> 1, half = j & 1;
        const char* src = pl ? (const char*)g_t2lo : (const char*)g_t2hi;
        int ph = half ^ ((row >> 2) & 1);
        *reinterpret_cast<float4*>(sm + pl * 8192 + row * 32 + ph * 16) =
            *reinterpret_cast<const float4*>(src + ((size_t)(b0 + row) * 16 + half * 8) * 2);
    }
    __syncthreads();

    // A fragments: 2 pairs covering this warp's 32 b rows, loaded once
    uint32_t aH[2][4], aL[2][4];
    const int cA = lane >> 4;
#pragma unroll
    for (int g = 0; g < 2; g++) {
        int rA = warp * 32 + g * 16 + (lane & 7) + ((lane >> 3) & 1) * 8;
        uint32_t aAddr = sb + rA * 32 + ((cA ^ ((rA >> 2) & 1))) * 16;
        ldm_x4(aH[g][0], aH[g][1], aH[g][2], aH[g][3], aAddr);
        ldm_x4(aL[g][0], aL[g][1], aL[g][2], aL[g][3], aAddr + 8192);
    }

    // B base: swizzle bit (rB>>2)&1 invariant under +16 row steps
    const int rB = (lane & 7) + (lane >> 4) * 8;
    const int cB = (lane >> 3) & 1;
    const uint32_t bBase = (uint32_t)(16384 + rB * 32 + ((cB ^ ((rB >> 2) & 1))) * 16);

    float mx[2][2];
#pragma unroll
    for (int g = 0; g < 2; g++) { mx[g][0] = -3.0e38f; mx[g][1] = -3.0e38f; }

    for (int c = 0; c < 4; c++) {
        __syncthreads();
        for (int i = t; i < 2048; i += 256) {
            int pl = i >> 10, j = i & 1023, row = j >> 1, half = j & 1;
            const char* src = pl ? (const char*)g_t1lo : (const char*)g_t1hi;
            int ph = half ^ ((row >> 2) & 1);
            *reinterpret_cast<float4*>(sm + 16384 + pl * 16384 + row * 32 + ph * 16) =
                *reinterpret_cast<const float4*>(
                    src + ((size_t)(mbase + c * 512 + row) * 16 + half * 8) * 2);
        }
        __syncthreads();

        uint32_t bAddr = sb + bBase;
        uint32_t bHa[4], bLa[4], bHb[4], bLb[4];
        ldm_x4(bHa[0], bHa[1], bHa[2], bHa[3], bAddr);
        ldm_x4(bLa[0], bLa[1], bLa[2], bLa[3], bAddr + 16384);

#pragma unroll 2
        for (int s = 0; s < 32; s += 2) {
            // prefetch step s+1
            ldm_x4(bHb[0], bHb[1], bHb[2], bHb[3], bAddr + 512);
            ldm_x4(bLb[0], bLb[1], bLb[2], bLb[3], bAddr + 512 + 16384);
            // compute step s with bHa/bLa
#pragma unroll
            for (int g = 0; g < 2; g++) {
                float a0[4] = {0.f, 0.f, 0.f, 0.f};
                float a1[4] = {0.f, 0.f, 0.f, 0.f};
                mma_bf16(a0, aH[g], bHa[0], bHa[1]);
                mma_bf16(a1, aH[g], bHa[2], bHa[3]);
                mma_bf16(a0, aH[g], bLa[0], bLa[1]);
                mma_bf16(a1, aH[g], bLa[2], bLa[3]);
                mma_bf16(a0, aL[g], bHa[0], bHa[1]);
                mma_bf16(a1, aL[g], bHa[2], bHa[3]);
                mx[g][0] = fmaxf(mx[g][0], fmaxf(fmaxf(a0[0], a0[1]), fmaxf(a1[0], a1[1])));
                mx[g][1] = fmaxf(mx[g][1], fmaxf(fmaxf(a0[2], a0[3]), fmaxf(a1[2], a1[3])));
            }
            // prefetch step s+2
            if (s + 2 < 32) {
                ldm_x4(bHa[0], bHa[1], bHa[2], bHa[3], bAddr + 1024);
                ldm_x4(bLa[0], bLa[1], bLa[2], bLa[3], bAddr + 1024 + 16384);
            }
            // compute step s+1 with bHb/bLb
#pragma unroll
            for (int g = 0; g < 2; g++) {
                float a0[4] = {0.f, 0.f, 0.f, 0.f};
                float a1[4] = {0.f, 0.f, 0.f, 0.f};
                mma_bf16(a0, aH[g], bHb[0], bHb[1]);
                mma_bf16(a1, aH[g], bHb[2], bHb[3]);
                mma_bf16(a0, aH[g], bLb[0], bLb[1]);
                mma_bf16(a1, aH[g], bLb[2], bLb[3]);
                mma_bf16(a0, aL[g], bHb[0], bHb[1]);
                mma_bf16(a1, aL[g], bHb[2], bHb[3]);
                mx[g][0] = fmaxf(mx[g][0], fmaxf(fmaxf(a0[0], a0[1]), fmaxf(a1[0], a1[1])));
                mx[g][1] = fmaxf(mx[g][1], fmaxf(fmaxf(a0[2], a0[3]), fmaxf(a1[2], a1[3])));
            }
            bAddr += 1024;
        }
    }

    // reduce across the 4 col-lanes sharing each row, then atomicMax
#pragma unroll
    for (int g = 0; g < 2; g++) {
        mx[g][0] = fmaxf(mx[g][0], __shfl_xor_sync(0xFFFFFFFF, mx[g][0], 1));
        mx[g][0] = fmaxf(mx[g][0], __shfl_xor_sync(0xFFFFFFFF, mx[g][0], 2));
        mx[g][1] = fmaxf(mx[g][1], __shfl_xor_sync(0xFFFFFFFF, mx[g][1], 1));
        mx[g][1] = fmaxf(mx[g][1], __shfl_xor_sync(0xFFFFFFFF, mx[g][1], 2));
    }
    if ((lane & 3) == 0) {
        const int base = b0 + warp * 32 + (lane >> 2);
#pragma unroll
        for (int g = 0; g < 2; g++) {
            atomicMax(&g_maxkey[base + g * 16], fkey(mx[g][0]));
            atomicMax(&g_maxkey[base + g * 16 + 8], fkey(mx[g][1]));
        }
    }
}

// ============================================================
__global__ void k_fin(float* __restrict__ out) {
    int b = blockIdx.x * blockDim.x + threadIdx.x;
    if (b < B_ROWS) out[b] = 23.0f * finv(g_maxkey[b]);
}

// ============================================================
extern "C" void kernel_launch(void* const* d_in, const int* in_sizes, int n_in,
                              void* d_out, int out_size) {
    const float* memory = (const float*)d_in[0];
    const float* value  = (const float*)d_in[1];
    const float* W1 = (const float*)d_in[2];
    const float* b1 = (const float*)d_in[3];
    const float* W2 = (const float*)d_in[4];
    const float* b2 = (const float*)d_in[5];
    const float* W3 = (const float*)d_in[6];
    const float* b3 = (const float*)d_in[7];
    const float* W4 = (const float*)d_in[8];
    const float* b4 = (const float*)d_in[9];

    cudaFuncSetAttribute(k_head, cudaFuncAttributeMaxDynamicSharedMemorySize, L1_SMEM);
    cudaFuncSetAttribute(k_l2, cudaFuncAttributeMaxDynamicSharedMemorySize, L2_SMEM);
    cudaFuncSetAttribute(k_l3, cudaFuncAttributeMaxDynamicSharedMemorySize, L3_SMEM);

    k_head<<<1040, 256, L1_SMEM>>>(memory, W1, b1, W2, W3, value);
    k_l2<<<dim3(10, 1024), 256, L2_SMEM>>>(b2);
    k_l3<<<L3_GRID, 256, L3_SMEM>>>(b3, b4, W4);
    k_sim_t<<<dim3(8, 32), 256>>>();
    k_fin<<<8, 256>>>((float*)d_out);
}